// round 1
// baseline (speedup 1.0000x reference)
#include <cuda_runtime.h>
#include <cuda_bf16.h>
#include <math.h>

#define Bz 32
#define Lz 768
#define Dz 256
#define Fz 256
#define Tz 3072

// Scratch (allocation-free: __device__ globals)
__device__ float g_buf1[Bz * Lz * Fz];
__device__ float g_buf2[Bz * Lz * Fz];
__device__ int   g_cum[Bz * Lz];

// ---------------------------------------------------------------------------
// Conv1d(K=3, pad=1) + bias + ReLU.  in: [B, L, Cin=256] -> out: [B, L, 256]
// Block: 256 threads (one per cout), TILE_L = 16 positions per block.
// ---------------------------------------------------------------------------
#define TILE_L 16

__global__ __launch_bounds__(256)
void conv_relu_kernel(const float* __restrict__ in,
                      const float* __restrict__ w,     // [3, 256, 256] k,cin,cout
                      const float* __restrict__ bias,  // [256]
                      float* __restrict__ out)
{
    __shared__ float xs[TILE_L + 2][256];

    const int tiles_per_row = Lz / TILE_L;            // 48
    const int b  = blockIdx.x / tiles_per_row;
    const int l0 = (blockIdx.x % tiles_per_row) * TILE_L;
    const int tid = threadIdx.x;

    const float* xrow = in + (size_t)b * Lz * 256;

    // Stage x tile with halo (zero padding at batch-row edges)
    for (int i = tid; i < (TILE_L + 2) * 256; i += 256) {
        int r = i >> 8;
        int c = i & 255;
        int gl = l0 - 1 + r;
        xs[r][c] = (gl >= 0 && gl < Lz) ? xrow[(size_t)gl * 256 + c] : 0.0f;
    }
    __syncthreads();

    const int cout = tid;
    float acc[TILE_L];
#pragma unroll
    for (int i = 0; i < TILE_L; i++) acc[i] = 0.0f;

    for (int cin = 0; cin < 256; ++cin) {
        float xr[TILE_L + 2];
#pragma unroll
        for (int r = 0; r < TILE_L + 2; r++) xr[r] = xs[r][cin];
#pragma unroll
        for (int k = 0; k < 3; k++) {
            float wv = w[((size_t)k * 256 + cin) * 256 + cout];
#pragma unroll
            for (int i = 0; i < TILE_L; i++)
                acc[i] = fmaf(xr[i + k], wv, acc[i]);
        }
    }

    float bv = bias[cout];
#pragma unroll
    for (int i = 0; i < TILE_L; i++) {
        float v = acc[i] + bv;
        out[((size_t)b * Lz + l0 + i) * 256 + cout] = fmaxf(v, 0.0f);
    }
}

// ---------------------------------------------------------------------------
// LayerNorm over last dim (256), in-place. Grid = B*L rows, block = 256.
// ---------------------------------------------------------------------------
__global__ __launch_bounds__(256)
void ln_kernel(float* __restrict__ io,
               const float* __restrict__ gamma,
               const float* __restrict__ beta)
{
    const int row = blockIdx.x;
    const int tid = threadIdx.x;

    float v = io[(size_t)row * 256 + tid];
    float s = v, sq = v * v;
#pragma unroll
    for (int o = 16; o; o >>= 1) {
        s  += __shfl_xor_sync(0xffffffffu, s,  o);
        sq += __shfl_xor_sync(0xffffffffu, sq, o);
    }
    __shared__ float ss[8], sqq[8];
    int wdx = tid >> 5;
    if ((tid & 31) == 0) { ss[wdx] = s; sqq[wdx] = sq; }
    __syncthreads();
    if (wdx == 0) {
        float a  = (tid < 8) ? ss[tid]  : 0.0f;
        float a2 = (tid < 8) ? sqq[tid] : 0.0f;
#pragma unroll
        for (int o = 4; o; o >>= 1) {
            a  += __shfl_xor_sync(0xffffffffu, a,  o);
            a2 += __shfl_xor_sync(0xffffffffu, a2, o);
        }
        if (tid == 0) { ss[0] = a; sqq[0] = a2; }
    }
    __syncthreads();
    float mu  = ss[0]  * (1.0f / 256.0f);
    float var = sqq[0] * (1.0f / 256.0f) - mu * mu;
    float rs  = rsqrtf(var + 1e-5f);
    io[(size_t)row * 256 + tid] = (v - mu) * rs * gamma[tid] + beta[tid];
}

// ---------------------------------------------------------------------------
// Linear (256 -> 1) + exp. One warp per row; grid = B*L/8 blocks of 256.
// ---------------------------------------------------------------------------
__global__ __launch_bounds__(256)
void linear_exp_kernel(const float* __restrict__ h,
                       const float* __restrict__ lin_w,  // [256]
                       const float* __restrict__ lin_b,  // [1]
                       float* __restrict__ dur_out)      // [B*L]
{
    const int warp = threadIdx.x >> 5;
    const int lane = threadIdx.x & 31;
    const int row = blockIdx.x * 8 + warp;

    float s = 0.0f;
#pragma unroll
    for (int j = lane; j < 256; j += 32)
        s = fmaf(h[(size_t)row * 256 + j], lin_w[j], s);
#pragma unroll
    for (int o = 16; o; o >>= 1)
        s += __shfl_xor_sync(0xffffffffu, s, o);
    if (lane == 0)
        dur_out[row] = expf(s + lin_b[0]);
}

// ---------------------------------------------------------------------------
// Per-batch inclusive cumsum of target (L=768) + write dpo (as float).
// Grid = B blocks of 768 threads.
// ---------------------------------------------------------------------------
__global__ __launch_bounds__(768)
void cumsum_kernel(const int* __restrict__ target,
                   float* __restrict__ dpo_out)
{
    __shared__ int s[Lz];
    const int b = blockIdx.x;
    const int tid = threadIdx.x;

    int tv = target[(size_t)b * Lz + tid];
    s[tid] = tv;
    for (int off = 1; off < Lz; off <<= 1) {
        __syncthreads();
        int v = (tid >= off) ? s[tid - off] : 0;
        __syncthreads();
        s[tid] += v;
    }
    __syncthreads();
    g_cum[(size_t)b * Lz + tid] = s[tid];
    dpo_out[(size_t)b * Lz + tid] = (float)tv;   // dpo = round(target*1.0) = target
}

// ---------------------------------------------------------------------------
// LR gather: out[b,t,:] = x[b, upper_bound(cum_b, t), :] * (t < total_b)
// Grid = (T/64, B); block = 256 threads (4 t's x 64 float4 lanes per iter).
// ---------------------------------------------------------------------------
__global__ __launch_bounds__(256)
void gather_kernel(const float* __restrict__ x,
                   float* __restrict__ dout)
{
    __shared__ int cum[Lz];
    const int b   = blockIdx.y;
    const int tid = threadIdx.x;

    for (int i = tid; i < Lz; i += 256)
        cum[i] = g_cum[(size_t)b * Lz + i];
    __syncthreads();

    const int total = cum[Lz - 1];
    const int t0 = blockIdx.x * 64;
    const int sub  = tid & 63;   // float4 lane over D=256
    const int tloc = tid >> 6;   // 0..3

    const float4* xrow = (const float4*)(x + (size_t)b * Lz * Dz);
    float4* orow = (float4*)(dout + (size_t)b * Tz * Dz);

#pragma unroll 4
    for (int it = 0; it < 16; ++it) {
        int t = t0 + it * 4 + tloc;
        // upper_bound: first idx with cum[idx] > t
        int lo = 0, hi = Lz;
        while (lo < hi) {
            int mid = (lo + hi) >> 1;
            if (cum[mid] <= t) lo = mid + 1; else hi = mid;
        }
        float4 v;
        if (t < total) {
            int idx = min(lo, Lz - 1);
            v = xrow[(size_t)idx * 64 + sub];
        } else {
            v = make_float4(0.0f, 0.0f, 0.0f, 0.0f);
        }
        orow[(size_t)t * 64 + sub] = v;
    }
}

// ---------------------------------------------------------------------------
// Launch
// ---------------------------------------------------------------------------
extern "C" void kernel_launch(void* const* d_in, const int* in_sizes, int n_in,
                              void* d_out, int out_size)
{
    const float* x       = (const float*)d_in[0];   // [B, L, D]
    const int*   target  = (const int*)  d_in[1];   // [B, L]
    // d_in[2] = mel_max_length (scalar, fixed to T=3072)
    const float* conv1_w = (const float*)d_in[3];
    const float* conv1_b = (const float*)d_in[4];
    const float* ln1_g   = (const float*)d_in[5];
    const float* ln1_b   = (const float*)d_in[6];
    const float* conv2_w = (const float*)d_in[7];
    const float* conv2_b = (const float*)d_in[8];
    const float* ln2_g   = (const float*)d_in[9];
    const float* ln2_b   = (const float*)d_in[10];
    const float* lin_w   = (const float*)d_in[11];
    const float* lin_b   = (const float*)d_in[12];

    float* out_gather = (float*)d_out;                           // [B, T, D]
    float* out_dpo    = out_gather + (size_t)Bz * Tz * Dz;       // [B, L]
    float* out_dur    = out_dpo + (size_t)Bz * Lz;               // [B, L]

    float* buf1; cudaGetSymbolAddress((void**)&buf1, g_buf1);
    float* buf2; cudaGetSymbolAddress((void**)&buf2, g_buf2);

    const int conv_blocks = (Bz * Lz) / TILE_L;   // 1536

    // Duration predictor path
    conv_relu_kernel<<<conv_blocks, 256>>>(x, conv1_w, conv1_b, buf1);
    ln_kernel<<<Bz * Lz, 256>>>(buf1, ln1_g, ln1_b);
    conv_relu_kernel<<<conv_blocks, 256>>>(buf1, conv2_w, conv2_b, buf2);
    ln_kernel<<<Bz * Lz, 256>>>(buf2, ln2_g, ln2_b);
    linear_exp_kernel<<<(Bz * Lz) / 8, 256>>>(buf2, lin_w, lin_b, out_dur);

    // dpo + cumsum
    cumsum_kernel<<<Bz, Lz>>>(target, out_dpo);

    // Length-regulator gather
    dim3 ggrid(Tz / 64, Bz);
    gather_kernel<<<ggrid, 256>>>(x, out_gather);
}

// round 3
// speedup vs baseline: 1.8134x; 1.8134x over previous
#include <cuda_runtime.h>
#include <cuda_bf16.h>
#include <math.h>
#include <stdint.h>

#define Bz 32
#define Lz 768
#define Dz 256
#define Fz 256
#define Tz 3072

// ---------------------------------------------------------------------------
// Scratch (allocation-free: __device__ globals)
// ---------------------------------------------------------------------------
__device__ __nv_bfloat16 g_xhi[Bz * Lz * Dz];
__device__ __nv_bfloat16 g_xlo[Bz * Lz * Dz];
__device__ __nv_bfloat16 g_h1h[Bz * Lz * Fz];
__device__ __nv_bfloat16 g_h1l[Bz * Lz * Fz];
__device__ uint32_t g_w1ph[3 * 128 * 256];      // conv1_w hi, k-pair packed
__device__ uint32_t g_w1pl[3 * 128 * 256];      // conv1_w lo
__device__ uint32_t g_w2ph[3 * 128 * 256];
__device__ uint32_t g_w2pl[3 * 128 * 256];
__device__ float    g_glw[256];                 // ln2_g * lin_w
__device__ float    g_scal[2];                  // {sum(g*lw), sum(b*lw)+lin_b}
__device__ int      g_cum[Bz * Lz];

// ---------------------------------------------------------------------------
// fp32 -> (hi, lo) bf16 pair helpers
// ---------------------------------------------------------------------------
__device__ __forceinline__ void split2(float a, float b,
                                       uint32_t& hi, uint32_t& lo)
{
    __nv_bfloat162 h = __floats2bfloat162_rn(a, b);
    float ra = a - __bfloat162float(h.x);
    float rb = b - __bfloat162float(h.y);
    __nv_bfloat162 l = __floats2bfloat162_rn(ra, rb);
    hi = *(uint32_t*)&h;
    lo = *(uint32_t*)&l;
}

// ---------------------------------------------------------------------------
// Prep: x fp32 -> split bf16 (8 elems/thread)
// ---------------------------------------------------------------------------
__global__ __launch_bounds__(256)
void prep_x(const float* __restrict__ x,
            __nv_bfloat16* __restrict__ ohi, __nv_bfloat16* __restrict__ olo)
{
    size_t i = ((size_t)blockIdx.x * 256 + threadIdx.x) * 8;
    float4 f0 = *(const float4*)(x + i);
    float4 f1 = *(const float4*)(x + i + 4);
    uint4 vh, vl;
    split2(f0.x, f0.y, vh.x, vl.x);
    split2(f0.z, f0.w, vh.y, vl.y);
    split2(f1.x, f1.y, vh.z, vl.z);
    split2(f1.z, f1.w, vh.w, vl.w);
    *(uint4*)(ohi + i) = vh;
    *(uint4*)(olo + i) = vl;
}

// ---------------------------------------------------------------------------
// Prep: weights [3,256,256] fp32 -> split bf16 k-pair-packed u32 [3,128,256]
// ---------------------------------------------------------------------------
__global__ __launch_bounds__(256)
void prep_w(const float* __restrict__ w1, const float* __restrict__ w2,
            uint32_t* __restrict__ p1h, uint32_t* __restrict__ p1l,
            uint32_t* __restrict__ p2h, uint32_t* __restrict__ p2l)
{
    int idx = blockIdx.x * 256 + threadIdx.x;          // 0 .. 98303
    const float* w = blockIdx.y ? w2 : w1;
    uint32_t* ph = blockIdx.y ? p2h : p1h;
    uint32_t* pl = blockIdx.y ? p2l : p1l;
    int n = idx & 255;
    int rest = idx >> 8;                                // k*128 + p
    int p = rest & 127, k = rest >> 7;
    float a = w[((size_t)(k * 256 + 2 * p)) * 256 + n];
    float b = w[((size_t)(k * 256 + 2 * p + 1)) * 256 + n];
    uint32_t hi, lo;
    split2(a, b, hi, lo);
    ph[idx] = hi;
    pl[idx] = lo;
}

// ---------------------------------------------------------------------------
// Prep: glw = ln2_g * lin_w ; scal = {sum(glw), sum(ln2_b*lin_w) + lin_b}
// ---------------------------------------------------------------------------
__global__ __launch_bounds__(256)
void prep_scal(const float* __restrict__ g, const float* __restrict__ bb,
               const float* __restrict__ lw, const float* __restrict__ lb,
               float* __restrict__ glw, float* __restrict__ scal)
{
    __shared__ float sg[8], sb[8];
    int t = threadIdx.x;
    float lwv = lw[t];
    float gv = g[t] * lwv;
    float bv = bb[t] * lwv;
    glw[t] = gv;
#pragma unroll
    for (int o = 16; o; o >>= 1) {
        gv += __shfl_xor_sync(0xffffffffu, gv, o);
        bv += __shfl_xor_sync(0xffffffffu, bv, o);
    }
    if ((t & 31) == 0) { sg[t >> 5] = gv; sb[t >> 5] = bv; }
    __syncthreads();
    if (t == 0) {
        float G = 0.f, Bv = 0.f;
        for (int i = 0; i < 8; i++) { G += sg[i]; Bv += sb[i]; }
        scal[0] = G;
        scal[1] = Bv + lb[0];
    }
}

// ---------------------------------------------------------------------------
// mma.sync m16n8k16 bf16 (fp32 accum)
// ---------------------------------------------------------------------------
__device__ __forceinline__ void mma16816(float* c, const uint32_t* a,
                                         uint32_t b0, uint32_t b1)
{
    asm volatile(
        "mma.sync.aligned.m16n8k16.row.col.f32.bf16.bf16.f32 "
        "{%0,%1,%2,%3}, {%4,%5,%6,%7}, {%8,%9}, {%0,%1,%2,%3};\n"
        : "+f"(c[0]), "+f"(c[1]), "+f"(c[2]), "+f"(c[3])
        : "r"(a[0]), "r"(a[1]), "r"(a[2]), "r"(a[3]), "r"(b0), "r"(b1));
}

// ---------------------------------------------------------------------------
// Fused conv1d(K=3,pad=1) + bias + ReLU + LN [+ linear+exp if FINAL]
// bf16x3 split precision: D = Ah*Bh + Al*Bh + Ah*Bl  (fp32 accumulate)
// CTA: M=128 x N=256, 512 threads (16 warps 4x4, warp tile 32x64).
// ---------------------------------------------------------------------------
template<bool FINAL>
__global__ __launch_bounds__(512)
void conv_mma(const __nv_bfloat16* __restrict__ Ahi,
              const __nv_bfloat16* __restrict__ Alo,
              const uint32_t* __restrict__ Wph,
              const uint32_t* __restrict__ Wpl,
              const float* __restrict__ bias,
              const float* __restrict__ gamma,
              const float* __restrict__ beta,
              const float* __restrict__ glw,
              const float* __restrict__ scal,
              __nv_bfloat16* __restrict__ outhi,
              __nv_bfloat16* __restrict__ outlo,
              float* __restrict__ dur)
{
    __shared__ __nv_bfloat16 Ash[128 * 40];   // A_hi tile 128x32, stride 40
    __shared__ __nv_bfloat16 Asl[128 * 40];   // A_lo tile
    __shared__ uint32_t Bs[16 * 264];         // B tile (hi or lo pass)
    __shared__ float svec[4][256];            // gamma, beta, bias, glw

    // Epilogue overlay (after mainloop)
    float* part = reinterpret_cast<float*>(Ash);   // [3][128][4]
    float* smu  = reinterpret_cast<float*>(Asl);   // [128]
    float* srs  = smu + 128;                       // [128]

    const int tid  = threadIdx.x;
    const int wid  = tid >> 5, lane = tid & 31;
    const int wm   = wid >> 2, wn = wid & 3;
    const int grp  = lane >> 2, tig = lane & 3;

    const int blk   = blockIdx.x;                  // 0..191
    const int batch = blk / 6;
    const int l0    = (blk % 6) * 128;
    const size_t rowbase = (size_t)batch * Lz;

    if (tid < 256) {
        svec[0][tid] = gamma[tid];
        svec[1][tid] = beta[tid];
        svec[2][tid] = bias[tid];
        svec[3][tid] = FINAL ? glw[tid] : 0.f;
    }

    float acc[2][8][4];
#pragma unroll
    for (int mt = 0; mt < 2; mt++)
#pragma unroll
        for (int nt = 0; nt < 8; nt++)
#pragma unroll
            for (int i = 0; i < 4; i++) acc[mt][nt][i] = 0.f;

    const int arow = tid >> 2;
    const int aseg = tid & 3;

    for (int c = 0; c < 24; ++c) {
        const int ks   = c >> 3;
        const int cin0 = (c & 7) << 5;
        const size_t woff = (size_t)ks * (128 * 256) + ((size_t)(cin0 >> 1)) * 256;
        __syncthreads();
        // --- load A chunk (hi + lo), halo rows zero outside batch ---
        {
            int gl = l0 + arow + ks - 1;
            int4 vh = make_int4(0, 0, 0, 0), vl = make_int4(0, 0, 0, 0);
            if (gl >= 0 && gl < Lz) {
                size_t off = (rowbase + gl) * 256 + cin0 + aseg * 8;
                vh = *(const int4*)(Ahi + off);
                vl = *(const int4*)(Alo + off);
            }
            *(int4*)(Ash + arow * 40 + aseg * 8) = vh;
            *(int4*)(Asl + arow * 40 + aseg * 8) = vl;
        }
        // --- load B_hi chunk ---
        {
            const uint32_t* src = Wph + woff;
#pragma unroll
            for (int i = 0; i < 8; ++i) {
                int idx = tid + i * 512;
                Bs[(idx >> 8) * 264 + (idx & 255)] = src[idx];
            }
        }
        __syncthreads();
        // --- phase 1: Ah*Bh + Al*Bh ---
#pragma unroll
        for (int kt = 0; kt < 2; ++kt) {
            uint32_t ah[2][4], al[2][4];
#pragma unroll
            for (int mt = 0; mt < 2; ++mt) {
                int boff = (wm * 32 + mt * 16 + grp) * 40 + kt * 16 + 2 * tig;
                ah[mt][0] = *(const uint32_t*)(Ash + boff);
                ah[mt][1] = *(const uint32_t*)(Ash + boff + 8 * 40);
                ah[mt][2] = *(const uint32_t*)(Ash + boff + 8);
                ah[mt][3] = *(const uint32_t*)(Ash + boff + 8 * 40 + 8);
                al[mt][0] = *(const uint32_t*)(Asl + boff);
                al[mt][1] = *(const uint32_t*)(Asl + boff + 8 * 40);
                al[mt][2] = *(const uint32_t*)(Asl + boff + 8);
                al[mt][3] = *(const uint32_t*)(Asl + boff + 8 * 40 + 8);
            }
#pragma unroll
            for (int nt = 0; nt < 8; ++nt) {
                int n = wn * 64 + nt * 8 + grp;
                uint32_t b0 = Bs[(kt * 8 + tig) * 264 + n];
                uint32_t b1 = Bs[(kt * 8 + 4 + tig) * 264 + n];
#pragma unroll
                for (int mt = 0; mt < 2; ++mt) {
                    mma16816(acc[mt][nt], ah[mt], b0, b1);
                    mma16816(acc[mt][nt], al[mt], b0, b1);
                }
            }
        }
        __syncthreads();
        // --- load B_lo chunk ---
        {
            const uint32_t* src = Wpl + woff;
#pragma unroll
            for (int i = 0; i < 8; ++i) {
                int idx = tid + i * 512;
                Bs[(idx >> 8) * 264 + (idx & 255)] = src[idx];
            }
        }
        __syncthreads();
        // --- phase 2: Ah*Bl ---
#pragma unroll
        for (int kt = 0; kt < 2; ++kt) {
            uint32_t ah[2][4];
#pragma unroll
            for (int mt = 0; mt < 2; ++mt) {
                int boff = (wm * 32 + mt * 16 + grp) * 40 + kt * 16 + 2 * tig;
                ah[mt][0] = *(const uint32_t*)(Ash + boff);
                ah[mt][1] = *(const uint32_t*)(Ash + boff + 8 * 40);
                ah[mt][2] = *(const uint32_t*)(Ash + boff + 8);
                ah[mt][3] = *(const uint32_t*)(Ash + boff + 8 * 40 + 8);
            }
#pragma unroll
            for (int nt = 0; nt < 8; ++nt) {
                int n = wn * 64 + nt * 8 + grp;
                uint32_t b0 = Bs[(kt * 8 + tig) * 264 + n];
                uint32_t b1 = Bs[(kt * 8 + 4 + tig) * 264 + n];
#pragma unroll
                for (int mt = 0; mt < 2; ++mt)
                    mma16816(acc[mt][nt], ah[mt], b0, b1);
            }
        }
    }
    __syncthreads();   // tiles free -> epilogue overlay

    // --- bias + ReLU + per-row partials ---
#pragma unroll
    for (int mt = 0; mt < 2; ++mt)
#pragma unroll
        for (int hf = 0; hf < 2; ++hf) {
            float s = 0.f, sq = 0.f, sd = 0.f;
#pragma unroll
            for (int nt = 0; nt < 8; ++nt) {
                int col = wn * 64 + nt * 8 + 2 * tig;
                float v0 = fmaxf(acc[mt][nt][hf * 2 + 0] + svec[2][col], 0.f);
                float v1 = fmaxf(acc[mt][nt][hf * 2 + 1] + svec[2][col + 1], 0.f);
                acc[mt][nt][hf * 2 + 0] = v0;
                acc[mt][nt][hf * 2 + 1] = v1;
                s += v0 + v1;
                sq += v0 * v0 + v1 * v1;
                if (FINAL) sd += v0 * svec[3][col] + v1 * svec[3][col + 1];
            }
            s  += __shfl_xor_sync(0xffffffffu, s, 1);
            s  += __shfl_xor_sync(0xffffffffu, s, 2);
            sq += __shfl_xor_sync(0xffffffffu, sq, 1);
            sq += __shfl_xor_sync(0xffffffffu, sq, 2);
            if (FINAL) {
                sd += __shfl_xor_sync(0xffffffffu, sd, 1);
                sd += __shfl_xor_sync(0xffffffffu, sd, 2);
            }
            if (tig == 0) {
                int row = wm * 32 + mt * 16 + hf * 8 + grp;
                part[0 * 512 + row * 4 + wn] = s;
                part[1 * 512 + row * 4 + wn] = sq;
                if (FINAL) part[2 * 512 + row * 4 + wn] = sd;
            }
        }
    __syncthreads();

    // --- row stats (+ duration for FINAL) ---
    if (tid < 128) {
        int row = tid;
        float s  = part[row * 4] + part[row * 4 + 1] + part[row * 4 + 2] + part[row * 4 + 3];
        float sq = part[512 + row * 4] + part[512 + row * 4 + 1] +
                   part[512 + row * 4 + 2] + part[512 + row * 4 + 3];
        float mu  = s * (1.f / 256.f);
        float var = sq * (1.f / 256.f) - mu * mu;
        float rs  = rsqrtf(var + 1e-5f);
        if (FINAL) {
            float s3 = part[1024 + row * 4] + part[1024 + row * 4 + 1] +
                       part[1024 + row * 4 + 2] + part[1024 + row * 4 + 3];
            dur[(size_t)blk * 128 + row] = expf(rs * (s3 - mu * scal[0]) + scal[1]);
        } else {
            smu[row] = mu;
            srs[row] = rs;
        }
    }

    if (!FINAL) {
        __syncthreads();
        // --- normalize + write split bf16 ---
#pragma unroll
        for (int mt = 0; mt < 2; ++mt)
#pragma unroll
            for (int hf = 0; hf < 2; ++hf) {
                int row = wm * 32 + mt * 16 + hf * 8 + grp;
                float mu = smu[row], rs = srs[row];
#pragma unroll
                for (int nt = 0; nt < 8; ++nt) {
                    int col = wn * 64 + nt * 8 + 2 * tig;
                    float v0 = (acc[mt][nt][hf * 2 + 0] - mu) * rs * svec[0][col] + svec[1][col];
                    float v1 = (acc[mt][nt][hf * 2 + 1] - mu) * rs * svec[0][col + 1] + svec[1][col + 1];
                    uint32_t hi, lo;
                    split2(v0, v1, hi, lo);
                    size_t off = ((size_t)blk * 128 + row) * 256 + col;
                    *(uint32_t*)(outhi + off) = hi;
                    *(uint32_t*)(outlo + off) = lo;
                }
            }
    }
}

// ---------------------------------------------------------------------------
// Per-batch inclusive cumsum of target (L=768) + write dpo (as float).
// ---------------------------------------------------------------------------
__global__ __launch_bounds__(768)
void cumsum_kernel(const int* __restrict__ target,
                   float* __restrict__ dpo_out)
{
    __shared__ int s[Lz];
    const int b = blockIdx.x;
    const int tid = threadIdx.x;

    int tv = target[(size_t)b * Lz + tid];
    s[tid] = tv;
    for (int off = 1; off < Lz; off <<= 1) {
        __syncthreads();
        int v = (tid >= off) ? s[tid - off] : 0;
        __syncthreads();
        s[tid] += v;
    }
    __syncthreads();
    g_cum[(size_t)b * Lz + tid] = s[tid];
    dpo_out[(size_t)b * Lz + tid] = (float)tv;
}

// ---------------------------------------------------------------------------
// LR gather: out[b,t,:] = x[b, upper_bound(cum_b, t), :] * (t < total_b)
// ---------------------------------------------------------------------------
__global__ __launch_bounds__(256)
void gather_kernel(const float* __restrict__ x,
                   float* __restrict__ dout)
{
    __shared__ int cum[Lz];
    const int b   = blockIdx.y;
    const int tid = threadIdx.x;

    for (int i = tid; i < Lz; i += 256)
        cum[i] = g_cum[(size_t)b * Lz + i];
    __syncthreads();

    const int total = cum[Lz - 1];
    const int t0 = blockIdx.x * 64;
    const int sub  = tid & 63;
    const int tloc = tid >> 6;

    const float4* xrow = (const float4*)(x + (size_t)b * Lz * Dz);
    float4* orow = (float4*)(dout + (size_t)b * Tz * Dz);

#pragma unroll 4
    for (int it = 0; it < 16; ++it) {
        int t = t0 + it * 4 + tloc;
        int lo = 0, hi = Lz;
        while (lo < hi) {
            int mid = (lo + hi) >> 1;
            if (cum[mid] <= t) lo = mid + 1; else hi = mid;
        }
        float4 v;
        if (t < total) {
            int idx = min(lo, Lz - 1);
            v = xrow[(size_t)idx * 64 + sub];
        } else {
            v = make_float4(0.0f, 0.0f, 0.0f, 0.0f);
        }
        orow[(size_t)t * 64 + sub] = v;
    }
}

// ---------------------------------------------------------------------------
// Launch
// ---------------------------------------------------------------------------
extern "C" void kernel_launch(void* const* d_in, const int* in_sizes, int n_in,
                              void* d_out, int out_size)
{
    const float* x       = (const float*)d_in[0];
    const int*   target  = (const int*)  d_in[1];
    const float* conv1_w = (const float*)d_in[3];
    const float* conv1_b = (const float*)d_in[4];
    const float* ln1_g   = (const float*)d_in[5];
    const float* ln1_b   = (const float*)d_in[6];
    const float* conv2_w = (const float*)d_in[7];
    const float* conv2_b = (const float*)d_in[8];
    const float* ln2_g   = (const float*)d_in[9];
    const float* ln2_b   = (const float*)d_in[10];
    const float* lin_w   = (const float*)d_in[11];
    const float* lin_b   = (const float*)d_in[12];

    float* out_gather = (float*)d_out;                        // [B, T, D]
    float* out_dpo    = out_gather + (size_t)Bz * Tz * Dz;    // [B, L]
    float* out_dur    = out_dpo + (size_t)Bz * Lz;            // [B, L]

    __nv_bfloat16 *xhi, *xlo, *h1h, *h1l;
    uint32_t *w1ph, *w1pl, *w2ph, *w2pl;
    float *glw, *scal;
    cudaGetSymbolAddress((void**)&xhi,  g_xhi);
    cudaGetSymbolAddress((void**)&xlo,  g_xlo);
    cudaGetSymbolAddress((void**)&h1h,  g_h1h);
    cudaGetSymbolAddress((void**)&h1l,  g_h1l);
    cudaGetSymbolAddress((void**)&w1ph, g_w1ph);
    cudaGetSymbolAddress((void**)&w1pl, g_w1pl);
    cudaGetSymbolAddress((void**)&w2ph, g_w2ph);
    cudaGetSymbolAddress((void**)&w2pl, g_w2pl);
    cudaGetSymbolAddress((void**)&glw,  g_glw);
    cudaGetSymbolAddress((void**)&scal, g_scal);

    // Prep
    prep_x<<<(Bz * Lz * Dz) / (256 * 8), 256>>>(x, xhi, xlo);
    prep_w<<<dim3(384, 2), 256>>>(conv1_w, conv2_w, w1ph, w1pl, w2ph, w2pl);
    prep_scal<<<1, 256>>>(ln2_g, ln2_b, lin_w, lin_b, glw, scal);

    // Fused duration-predictor path (bf16x3 split-precision GEMMs)
    conv_mma<false><<<192, 512>>>(xhi, xlo, w1ph, w1pl, conv1_b, ln1_g, ln1_b,
                                  glw, scal, h1h, h1l, nullptr);
    conv_mma<true ><<<192, 512>>>(h1h, h1l, w2ph, w2pl, conv2_b, ln2_g, ln2_b,
                                  glw, scal, nullptr, nullptr, out_dur);

    // dpo + cumsum
    cumsum_kernel<<<Bz, Lz>>>(target, out_dpo);

    // Length-regulator gather
    dim3 ggrid(Tz / 64, Bz);
    gather_kernel<<<ggrid, 256>>>(x, out_gather);
}

// round 5
// speedup vs baseline: 2.1443x; 1.1825x over previous
#include <cuda_runtime.h>
#include <cuda_bf16.h>
#include <math.h>
#include <stdint.h>

#define Bz 32
#define Lz 768
#define Dz 256
#define Fz 256
#define Tz 3072

// ---------------------------------------------------------------------------
// Scratch (allocation-free: __device__ globals)
// ---------------------------------------------------------------------------
__device__ __nv_bfloat16 g_xhi[Bz * Lz * Dz];
__device__ __nv_bfloat16 g_xlo[Bz * Lz * Dz];
__device__ __nv_bfloat16 g_h1h[Bz * Lz * Fz];
__device__ __nv_bfloat16 g_h1l[Bz * Lz * Fz];
// weights re-packed: [tap][cout][pair] u32, pair = (bf16 cin=2p, cin=2p+1)
__device__ uint32_t g_w1ph[3 * 256 * 128];
__device__ uint32_t g_w1pl[3 * 256 * 128];
__device__ uint32_t g_w2ph[3 * 256 * 128];
__device__ uint32_t g_w2pl[3 * 256 * 128];
__device__ float    g_glw[256];                 // ln2_g * lin_w
__device__ float    g_scal[2];                  // {sum(g*lw), sum(b*lw)+lin_b}
__device__ int      g_cum[Bz * Lz];

// ---------------------------------------------------------------------------
// helpers
// ---------------------------------------------------------------------------
__device__ __forceinline__ uint32_t smem_u32(const void* p) {
    uint32_t a;
    asm("{ .reg .u64 t; cvta.to.shared.u64 t, %1; cvt.u32.u64 %0, t; }"
        : "=r"(a) : "l"(p));
    return a;
}

// cp.async 16B with zero-fill (src_bytes = 0 or 16)
__device__ __forceinline__ void cp16(uint32_t dst, const void* src, int src_bytes) {
    asm volatile("cp.async.cg.shared.global [%0], [%1], 16, %2;"
                 :: "r"(dst), "l"(src), "r"(src_bytes) : "memory");
}
#define CP_COMMIT() asm volatile("cp.async.commit_group;" ::: "memory")
#define CP_WAIT(n)  asm volatile("cp.async.wait_group %0;" :: "n"(n) : "memory")

__device__ __forceinline__ void mma16816(float* c, const uint32_t* a,
                                         uint32_t b0, uint32_t b1)
{
    asm volatile(
        "mma.sync.aligned.m16n8k16.row.col.f32.bf16.bf16.f32 "
        "{%0,%1,%2,%3}, {%4,%5,%6,%7}, {%8,%9}, {%0,%1,%2,%3};\n"
        : "+f"(c[0]), "+f"(c[1]), "+f"(c[2]), "+f"(c[3])
        : "r"(a[0]), "r"(a[1]), "r"(a[2]), "r"(a[3]), "r"(b0), "r"(b1));
}

__device__ __forceinline__ void split2(float a, float b, uint32_t& hi, uint32_t& lo)
{
    __nv_bfloat162 h = __floats2bfloat162_rn(a, b);
    float ra = a - __bfloat162float(h.x);
    float rb = b - __bfloat162float(h.y);
    __nv_bfloat162 l = __floats2bfloat162_rn(ra, rb);
    hi = *(uint32_t*)&h;
    lo = *(uint32_t*)&l;
}

// ---------------------------------------------------------------------------
// Prep kernels
// ---------------------------------------------------------------------------
__global__ __launch_bounds__(256)
void prep_x(const float* __restrict__ x,
            __nv_bfloat16* __restrict__ ohi, __nv_bfloat16* __restrict__ olo)
{
    size_t i = ((size_t)blockIdx.x * 256 + threadIdx.x) * 8;
    float4 f0 = *(const float4*)(x + i);
    float4 f1 = *(const float4*)(x + i + 4);
    uint4 vh, vl;
    split2(f0.x, f0.y, vh.x, vl.x);
    split2(f0.z, f0.w, vh.y, vl.y);
    split2(f1.x, f1.y, vh.z, vl.z);
    split2(f1.z, f1.w, vh.w, vl.w);
    *(uint4*)(ohi + i) = vh;
    *(uint4*)(olo + i) = vl;
}

// weights [3,256,256] (tap,cin,cout) fp32 -> [tap][cout][pair] split u32
__global__ __launch_bounds__(256)
void prep_w(const float* __restrict__ w1, const float* __restrict__ w2,
            uint32_t* __restrict__ p1h, uint32_t* __restrict__ p1l,
            uint32_t* __restrict__ p2h, uint32_t* __restrict__ p2l)
{
    int idx = blockIdx.x * 256 + threadIdx.x;          // 0 .. 98303
    const float* w = blockIdx.y ? w2 : w1;
    uint32_t* ph = blockIdx.y ? p2h : p1h;
    uint32_t* pl = blockIdx.y ? p2l : p1l;
    int p   = idx & 127;
    int n   = (idx >> 7) & 255;
    int tap = idx >> 15;
    float a = w[((size_t)(tap * 256 + 2 * p))     * 256 + n];
    float b = w[((size_t)(tap * 256 + 2 * p + 1)) * 256 + n];
    uint32_t hi, lo;
    split2(a, b, hi, lo);
    ph[idx] = hi;
    pl[idx] = lo;
}

__global__ __launch_bounds__(256)
void prep_scal(const float* __restrict__ g, const float* __restrict__ bb,
               const float* __restrict__ lw, const float* __restrict__ lb,
               float* __restrict__ glw, float* __restrict__ scal)
{
    __shared__ float sg[8], sb[8];
    int t = threadIdx.x;
    float lwv = lw[t];
    float gv = g[t] * lwv;
    float bv = bb[t] * lwv;
    glw[t] = gv;
#pragma unroll
    for (int o = 16; o; o >>= 1) {
        gv += __shfl_xor_sync(0xffffffffu, gv, o);
        bv += __shfl_xor_sync(0xffffffffu, bv, o);
    }
    if ((t & 31) == 0) { sg[t >> 5] = gv; sb[t >> 5] = bv; }
    __syncthreads();
    if (t == 0) {
        float G = 0.f, Bv = 0.f;
        for (int i = 0; i < 8; i++) { G += sg[i]; Bv += sb[i]; }
        scal[0] = G;
        scal[1] = Bv + lb[0];
    }
}

// ---------------------------------------------------------------------------
// Fused conv1d(K=3,pad=1) + bias + ReLU + LN [+ linear+exp if FINAL]
// bf16x3 split: D = Ah*Bh + Al*Bh + Ah*Bl  (fp32 accumulate)
// CTA: 256 thr (8 warps, 2M x 4N), tile M=64 x N=256, 2 CTAs/SM.
// K = 768 in 24 chunks of 32 (tap-major), cp.async double-buffered.
// Smem layout per stage:
//   A_hi  64x32 bf16, stride 40  (5120 B)   -> conflict-free frag loads
//   A_lo  same                   (5120 B)
//   B_hi  256 n x 16 pairs u32, stride 20 (20480 B) -> conflict-free
//   B_lo  same                   (20480 B)
// ---------------------------------------------------------------------------
#define SA_H 0
#define SA_L 5120
#define SB_H 10240
#define SB_L 30720
#define STAGE 51200
#define STAGE0_OFF 4096
#define CONV_SMEM (STAGE0_OFF + 2 * STAGE)   // 106496

__device__ __forceinline__ void load_chunk(
    uint32_t stg, int c, int tid, int l0, size_t rowbase,
    const __nv_bfloat16* __restrict__ Ahi, const __nv_bfloat16* __restrict__ Alo,
    const uint32_t* __restrict__ Wph, const uint32_t* __restrict__ Wpl)
{
    const int tap  = c >> 3;
    const int cin0 = (c & 7) << 5;
    // A: 64 rows x 64B (4 segs of 16B); one (row,seg) per thread
    {
        int row = tid >> 2, seg = tid & 3;
        int gl = l0 + row + tap - 1;
        int ok = (gl >= 0 && gl < Lz) ? 16 : 0;
        int glc = gl < 0 ? 0 : (gl >= Lz ? Lz - 1 : gl);
        size_t off = ((rowbase + glc) << 8) + cin0 + (seg << 3);
        uint32_t d = row * 80 + seg * 16;
        cp16(stg + SA_H + d, Ahi + off, ok);
        cp16(stg + SA_L + d, Alo + off, ok);
    }
    // B: 256 n x 16 pairs u32 (4 segs of 16B per n)
    const int p0 = (c & 7) << 4;
    const uint32_t* bh = Wph + (size_t)tap * 256 * 128 + p0;
    const uint32_t* bl = Wpl + (size_t)tap * 256 * 128 + p0;
#pragma unroll
    for (int i = 0; i < 4; ++i) {
        int idx = tid + (i << 8);            // 0..1023
        int n = idx >> 2, seg = idx & 3;
        uint32_t d = n * 80 + seg * 16;
        cp16(stg + SB_H + d, bh + n * 128 + seg * 4, 16);
        cp16(stg + SB_L + d, bl + n * 128 + seg * 4, 16);
    }
}

template<bool FINAL>
__global__ void __launch_bounds__(256, 2)
conv_mma2(const __nv_bfloat16* __restrict__ Ahi, const __nv_bfloat16* __restrict__ Alo,
          const uint32_t* __restrict__ Wph, const uint32_t* __restrict__ Wpl,
          const float* __restrict__ bias, const float* __restrict__ gamma,
          const float* __restrict__ beta, const float* __restrict__ glw,
          const float* __restrict__ scal,
          __nv_bfloat16* __restrict__ outhi, __nv_bfloat16* __restrict__ outlo,
          float* __restrict__ dur)
{
    extern __shared__ char smem[];
    const uint32_t sb = smem_u32(smem);
    float* svec = (float*)smem;                       // [4][256]
    const uint32_t stage0 = sb + STAGE0_OFF;

    const int tid = threadIdx.x;
    const int wid = tid >> 5, lane = tid & 31;
    const int wm = wid >> 2, wn = wid & 3;            // 2M x 4N warps
    const int grp = lane >> 2, tig = lane & 3;

    const int blk = blockIdx.x;                       // 0..383
    const int batch = blk / 12;
    const int l0 = (blk % 12) * 64;
    const size_t rowbase = (size_t)batch * Lz;

    svec[tid]       = bias[tid];
    svec[256 + tid] = gamma[tid];
    svec[512 + tid] = beta[tid];
    svec[768 + tid] = FINAL ? glw[tid] : 0.f;

    float acc[2][8][4];
#pragma unroll
    for (int mt = 0; mt < 2; mt++)
#pragma unroll
        for (int nt = 0; nt < 8; nt++)
#pragma unroll
            for (int i = 0; i < 4; i++) acc[mt][nt][i] = 0.f;

    load_chunk(stage0,         0, tid, l0, rowbase, Ahi, Alo, Wph, Wpl);
    CP_COMMIT();
    load_chunk(stage0 + STAGE, 1, tid, l0, rowbase, Ahi, Alo, Wph, Wpl);
    CP_COMMIT();

    for (int c = 0; c < 24; ++c) {
        const uint32_t stg = stage0 + (c & 1) * STAGE;
        if (c < 23) CP_WAIT(1); else CP_WAIT(0);
        __syncthreads();

        const __nv_bfloat16* Ash = (const __nv_bfloat16*)(smem + (stg - sb) + SA_H);
        const __nv_bfloat16* Asl = (const __nv_bfloat16*)(smem + (stg - sb) + SA_L);
        const uint32_t* Bsh = (const uint32_t*)(smem + (stg - sb) + SB_H);
        const uint32_t* Bsl = (const uint32_t*)(smem + (stg - sb) + SB_L);

#pragma unroll
        for (int kt = 0; kt < 2; ++kt) {
            uint32_t ah[2][4], al[2][4];
#pragma unroll
            for (int mt = 0; mt < 2; ++mt) {
                int ro = (wm * 32 + mt * 16 + grp) * 40 + kt * 16 + 2 * tig;
                ah[mt][0] = *(const uint32_t*)(Ash + ro);
                ah[mt][1] = *(const uint32_t*)(Ash + ro + 8 * 40);
                ah[mt][2] = *(const uint32_t*)(Ash + ro + 8);
                ah[mt][3] = *(const uint32_t*)(Ash + ro + 8 * 40 + 8);
                al[mt][0] = *(const uint32_t*)(Asl + ro);
                al[mt][1] = *(const uint32_t*)(Asl + ro + 8 * 40);
                al[mt][2] = *(const uint32_t*)(Asl + ro + 8);
                al[mt][3] = *(const uint32_t*)(Asl + ro + 8 * 40 + 8);
            }
#pragma unroll
            for (int nt = 0; nt < 8; ++nt) {
                int n = wn * 64 + nt * 8 + grp;
                int bo = n * 20 + kt * 8 + tig;
                uint32_t b0h = Bsh[bo], b1h = Bsh[bo + 4];
                uint32_t b0l = Bsl[bo], b1l = Bsl[bo + 4];
#pragma unroll
                for (int mt = 0; mt < 2; ++mt) {
                    mma16816(acc[mt][nt], ah[mt], b0h, b1h);
                    mma16816(acc[mt][nt], al[mt], b0h, b1h);
                    mma16816(acc[mt][nt], ah[mt], b0l, b1l);
                }
            }
        }
        __syncthreads();
        if (c + 2 < 24) {
            load_chunk(stg, c + 2, tid, l0, rowbase, Ahi, Alo, Wph, Wpl);
            CP_COMMIT();
        }
    }

    // ----- epilogue: overlay reduction arrays on stage0 region -----
    float* part = (float*)(smem + STAGE0_OFF);    // [3][64][4]
    float* smu  = part + 3 * 64 * 4;              // [64]
    float* srs  = smu + 64;                       // [64]

#pragma unroll
    for (int mt = 0; mt < 2; ++mt)
#pragma unroll
        for (int hf = 0; hf < 2; ++hf) {
            float s = 0.f, sq = 0.f, sd = 0.f;
#pragma unroll
            for (int nt = 0; nt < 8; ++nt) {
                int col = wn * 64 + nt * 8 + 2 * tig;
                float v0 = fmaxf(acc[mt][nt][hf * 2 + 0] + svec[col], 0.f);
                float v1 = fmaxf(acc[mt][nt][hf * 2 + 1] + svec[col + 1], 0.f);
                acc[mt][nt][hf * 2 + 0] = v0;
                acc[mt][nt][hf * 2 + 1] = v1;
                s += v0 + v1;
                sq += v0 * v0 + v1 * v1;
                if (FINAL) sd += v0 * svec[768 + col] + v1 * svec[768 + col + 1];
            }
            s  += __shfl_xor_sync(0xffffffffu, s, 1);
            s  += __shfl_xor_sync(0xffffffffu, s, 2);
            sq += __shfl_xor_sync(0xffffffffu, sq, 1);
            sq += __shfl_xor_sync(0xffffffffu, sq, 2);
            if (FINAL) {
                sd += __shfl_xor_sync(0xffffffffu, sd, 1);
                sd += __shfl_xor_sync(0xffffffffu, sd, 2);
            }
            if (tig == 0) {
                int row = wm * 32 + mt * 16 + hf * 8 + grp;
                part[0 * 256 + row * 4 + wn] = s;
                part[1 * 256 + row * 4 + wn] = sq;
                if (FINAL) part[2 * 256 + row * 4 + wn] = sd;
            }
        }
    __syncthreads();

    if (tid < 64) {
        int row = tid;
        float s  = part[row * 4] + part[row * 4 + 1] + part[row * 4 + 2] + part[row * 4 + 3];
        float sq = part[256 + row * 4] + part[256 + row * 4 + 1] +
                   part[256 + row * 4 + 2] + part[256 + row * 4 + 3];
        float mu  = s * (1.f / 256.f);
        float var = sq * (1.f / 256.f) - mu * mu;
        float rs  = rsqrtf(var + 1e-5f);
        if (FINAL) {
            float s3 = part[512 + row * 4] + part[512 + row * 4 + 1] +
                       part[512 + row * 4 + 2] + part[512 + row * 4 + 3];
            dur[(size_t)blk * 64 + row] = expf(rs * (s3 - mu * scal[0]) + scal[1]);
        } else {
            smu[row] = mu;
            srs[row] = rs;
        }
    }

    if (!FINAL) {
        __syncthreads();
#pragma unroll
        for (int mt = 0; mt < 2; ++mt)
#pragma unroll
            for (int hf = 0; hf < 2; ++hf) {
                int row = wm * 32 + mt * 16 + hf * 8 + grp;
                float mu = smu[row], rs = srs[row];
#pragma unroll
                for (int nt = 0; nt < 8; ++nt) {
                    int col = wn * 64 + nt * 8 + 2 * tig;
                    float v0 = (acc[mt][nt][hf * 2 + 0] - mu) * rs * svec[256 + col]     + svec[512 + col];
                    float v1 = (acc[mt][nt][hf * 2 + 1] - mu) * rs * svec[256 + col + 1] + svec[512 + col + 1];
                    uint32_t hi, lo;
                    split2(v0, v1, hi, lo);
                    size_t off = ((size_t)blk * 64 + row) * 256 + col;
                    *(uint32_t*)(outhi + off) = hi;
                    *(uint32_t*)(outlo + off) = lo;
                }
            }
    }
}

// ---------------------------------------------------------------------------
// Per-batch inclusive cumsum of target (L=768) + write dpo (as float).
// ---------------------------------------------------------------------------
__global__ __launch_bounds__(768)
void cumsum_kernel(const int* __restrict__ target,
                   float* __restrict__ dpo_out)
{
    __shared__ int s[Lz];
    const int b = blockIdx.x;
    const int tid = threadIdx.x;

    int tv = target[(size_t)b * Lz + tid];
    s[tid] = tv;
    for (int off = 1; off < Lz; off <<= 1) {
        __syncthreads();
        int v = (tid >= off) ? s[tid - off] : 0;
        __syncthreads();
        s[tid] += v;
    }
    __syncthreads();
    g_cum[(size_t)b * Lz + tid] = s[tid];
    dpo_out[(size_t)b * Lz + tid] = (float)tv;
}

// ---------------------------------------------------------------------------
// LR gather: out[b,t,:] = x[b, upper_bound(cum_b, t), :] * (t < total_b)
// ---------------------------------------------------------------------------
__global__ __launch_bounds__(256)
void gather_kernel(const float* __restrict__ x,
                   float* __restrict__ dout)
{
    __shared__ int cum[Lz];
    const int b   = blockIdx.y;
    const int tid = threadIdx.x;

    for (int i = tid; i < Lz; i += 256)
        cum[i] = g_cum[(size_t)b * Lz + i];
    __syncthreads();

    const int total = cum[Lz - 1];
    const int t0 = blockIdx.x * 64;
    const int sub  = tid & 63;
    const int tloc = tid >> 6;

    const float4* xrow = (const float4*)(x + (size_t)b * Lz * Dz);
    float4* orow = (float4*)(dout + (size_t)b * Tz * Dz);

#pragma unroll 4
    for (int it = 0; it < 16; ++it) {
        int t = t0 + it * 4 + tloc;
        int lo = 0, hi = Lz;
        while (lo < hi) {
            int mid = (lo + hi) >> 1;
            if (cum[mid] <= t) lo = mid + 1; else hi = mid;
        }
        float4 v;
        if (t < total) {
            int idx = min(lo, Lz - 1);
            v = xrow[(size_t)idx * 64 + sub];
        } else {
            v = make_float4(0.0f, 0.0f, 0.0f, 0.0f);
        }
        orow[(size_t)t * 64 + sub] = v;
    }
}

// ---------------------------------------------------------------------------
// Launch
// ---------------------------------------------------------------------------
extern "C" void kernel_launch(void* const* d_in, const int* in_sizes, int n_in,
                              void* d_out, int out_size)
{
    const float* x       = (const float*)d_in[0];
    const int*   target  = (const int*)  d_in[1];
    const float* conv1_w = (const float*)d_in[3];
    const float* conv1_b = (const float*)d_in[4];
    const float* ln1_g   = (const float*)d_in[5];
    const float* ln1_b   = (const float*)d_in[6];
    const float* conv2_w = (const float*)d_in[7];
    const float* conv2_b = (const float*)d_in[8];
    const float* ln2_g   = (const float*)d_in[9];
    const float* ln2_b   = (const float*)d_in[10];
    const float* lin_w   = (const float*)d_in[11];
    const float* lin_b   = (const float*)d_in[12];

    float* out_gather = (float*)d_out;                        // [B, T, D]
    float* out_dpo    = out_gather + (size_t)Bz * Tz * Dz;    // [B, L]
    float* out_dur    = out_dpo + (size_t)Bz * Lz;            // [B, L]

    __nv_bfloat16 *xhi, *xlo, *h1h, *h1l;
    uint32_t *w1ph, *w1pl, *w2ph, *w2pl;
    float *glw, *scal;
    cudaGetSymbolAddress((void**)&xhi,  g_xhi);
    cudaGetSymbolAddress((void**)&xlo,  g_xlo);
    cudaGetSymbolAddress((void**)&h1h,  g_h1h);
    cudaGetSymbolAddress((void**)&h1l,  g_h1l);
    cudaGetSymbolAddress((void**)&w1ph, g_w1ph);
    cudaGetSymbolAddress((void**)&w1pl, g_w1pl);
    cudaGetSymbolAddress((void**)&w2ph, g_w2ph);
    cudaGetSymbolAddress((void**)&w2pl, g_w2pl);
    cudaGetSymbolAddress((void**)&glw,  g_glw);
    cudaGetSymbolAddress((void**)&scal, g_scal);

    cudaFuncSetAttribute(conv_mma2<false>, cudaFuncAttributeMaxDynamicSharedMemorySize, CONV_SMEM);
    cudaFuncSetAttribute(conv_mma2<true>,  cudaFuncAttributeMaxDynamicSharedMemorySize, CONV_SMEM);

    // Prep
    prep_x<<<(Bz * Lz * Dz) / (256 * 8), 256>>>(x, xhi, xlo);
    prep_w<<<dim3(384, 2), 256>>>(conv1_w, conv2_w, w1ph, w1pl, w2ph, w2pl);
    prep_scal<<<1, 256>>>(ln2_g, ln2_b, lin_w, lin_b, glw, scal);

    // Fused duration-predictor path (bf16x3 split-precision GEMMs)
    conv_mma2<false><<<384, 256, CONV_SMEM>>>(xhi, xlo, w1ph, w1pl, conv1_b, ln1_g, ln1_b,
                                              glw, scal, h1h, h1l, nullptr);
    conv_mma2<true ><<<384, 256, CONV_SMEM>>>(h1h, h1l, w2ph, w2pl, conv2_b, ln2_g, ln2_b,
                                              glw, scal, nullptr, nullptr, out_dur);

    // dpo + cumsum
    cumsum_kernel<<<Bz, Lz>>>(target, out_dpo);

    // Length-regulator gather
    dim3 ggrid(Tz / 64, Bz);
    gather_kernel<<<ggrid, 256>>>(x, out_gather);
}

// round 6
// speedup vs baseline: 2.2359x; 1.0428x over previous
#include <cuda_runtime.h>
#include <cuda_bf16.h>
#include <math.h>
#include <stdint.h>

#define Bz 32
#define Lz 768
#define Dz 256
#define Fz 256
#define Tz 3072

// ---------------------------------------------------------------------------
// Scratch (allocation-free: __device__ globals)
// ---------------------------------------------------------------------------
__device__ __nv_bfloat16 g_xhi[Bz * Lz * Dz];
__device__ __nv_bfloat16 g_xlo[Bz * Lz * Dz];
__device__ __nv_bfloat16 g_h1h[Bz * Lz * Fz];
__device__ __nv_bfloat16 g_h1l[Bz * Lz * Fz];
// weights re-packed: [tap][cout][pair] u32, pair = (bf16 cin=2p, cin=2p+1)
__device__ uint32_t g_w1ph[3 * 256 * 128];
__device__ uint32_t g_w1pl[3 * 256 * 128];
__device__ uint32_t g_w2ph[3 * 256 * 128];
__device__ uint32_t g_w2pl[3 * 256 * 128];
__device__ float    g_glw[256];                 // ln2_g * lin_w
__device__ float    g_scal[2];                  // {sum(g*lw), sum(b*lw)+lin_b}
__device__ int      g_cum[Bz * Lz];

// ---------------------------------------------------------------------------
// helpers
// ---------------------------------------------------------------------------
__device__ __forceinline__ uint32_t smem_u32(const void* p) {
    uint32_t a;
    asm("{ .reg .u64 t; cvta.to.shared.u64 t, %1; cvt.u32.u64 %0, t; }"
        : "=r"(a) : "l"(p));
    return a;
}

// cp.async 16B with zero-fill (src_bytes = 0 or 16)
__device__ __forceinline__ void cp16(uint32_t dst, const void* src, int src_bytes) {
    asm volatile("cp.async.cg.shared.global [%0], [%1], 16, %2;"
                 :: "r"(dst), "l"(src), "r"(src_bytes) : "memory");
}
#define CP_COMMIT() asm volatile("cp.async.commit_group;" ::: "memory")
#define CP_WAIT(n)  asm volatile("cp.async.wait_group %0;" :: "n"(n) : "memory")

#define LDSM_X4(r, addr) \
    asm volatile("ldmatrix.sync.aligned.m8n8.x4.shared.b16 {%0,%1,%2,%3}, [%4];" \
        : "=r"((r)[0]), "=r"((r)[1]), "=r"((r)[2]), "=r"((r)[3]) : "r"(addr))

__device__ __forceinline__ void mma16816(float* c, const uint32_t* a,
                                         uint32_t b0, uint32_t b1)
{
    asm volatile(
        "mma.sync.aligned.m16n8k16.row.col.f32.bf16.bf16.f32 "
        "{%0,%1,%2,%3}, {%4,%5,%6,%7}, {%8,%9}, {%0,%1,%2,%3};\n"
        : "+f"(c[0]), "+f"(c[1]), "+f"(c[2]), "+f"(c[3])
        : "r"(a[0]), "r"(a[1]), "r"(a[2]), "r"(a[3]), "r"(b0), "r"(b1));
}

__device__ __forceinline__ void split2(float a, float b, uint32_t& hi, uint32_t& lo)
{
    __nv_bfloat162 h = __floats2bfloat162_rn(a, b);
    float ra = a - __bfloat162float(h.x);
    float rb = b - __bfloat162float(h.y);
    __nv_bfloat162 l = __floats2bfloat162_rn(ra, rb);
    hi = *(uint32_t*)&h;
    lo = *(uint32_t*)&l;
}

// ---------------------------------------------------------------------------
// Prep kernels
// ---------------------------------------------------------------------------
__global__ __launch_bounds__(256)
void prep_x(const float* __restrict__ x,
            __nv_bfloat16* __restrict__ ohi, __nv_bfloat16* __restrict__ olo)
{
    size_t i = ((size_t)blockIdx.x * 256 + threadIdx.x) * 8;
    float4 f0 = *(const float4*)(x + i);
    float4 f1 = *(const float4*)(x + i + 4);
    uint4 vh, vl;
    split2(f0.x, f0.y, vh.x, vl.x);
    split2(f0.z, f0.w, vh.y, vl.y);
    split2(f1.x, f1.y, vh.z, vl.z);
    split2(f1.z, f1.w, vh.w, vl.w);
    *(uint4*)(ohi + i) = vh;
    *(uint4*)(olo + i) = vl;
}

// weights [3,256,256] (tap,cin,cout) fp32 -> [tap][cout][pair] split u32
__global__ __launch_bounds__(256)
void prep_w(const float* __restrict__ w1, const float* __restrict__ w2,
            uint32_t* __restrict__ p1h, uint32_t* __restrict__ p1l,
            uint32_t* __restrict__ p2h, uint32_t* __restrict__ p2l)
{
    int idx = blockIdx.x * 256 + threadIdx.x;          // 0 .. 98303
    const float* w = blockIdx.y ? w2 : w1;
    uint32_t* ph = blockIdx.y ? p2h : p1h;
    uint32_t* pl = blockIdx.y ? p2l : p1l;
    int p   = idx & 127;
    int n   = (idx >> 7) & 255;
    int tap = idx >> 15;
    float a = w[((size_t)(tap * 256 + 2 * p))     * 256 + n];
    float b = w[((size_t)(tap * 256 + 2 * p + 1)) * 256 + n];
    uint32_t hi, lo;
    split2(a, b, hi, lo);
    ph[idx] = hi;
    pl[idx] = lo;
}

__global__ __launch_bounds__(256)
void prep_scal(const float* __restrict__ g, const float* __restrict__ bb,
               const float* __restrict__ lw, const float* __restrict__ lb,
               float* __restrict__ glw, float* __restrict__ scal)
{
    __shared__ float sg[8], sb[8];
    int t = threadIdx.x;
    float lwv = lw[t];
    float gv = g[t] * lwv;
    float bv = bb[t] * lwv;
    glw[t] = gv;
#pragma unroll
    for (int o = 16; o; o >>= 1) {
        gv += __shfl_xor_sync(0xffffffffu, gv, o);
        bv += __shfl_xor_sync(0xffffffffu, bv, o);
    }
    if ((t & 31) == 0) { sg[t >> 5] = gv; sb[t >> 5] = bv; }
    __syncthreads();
    if (t == 0) {
        float G = 0.f, Bv = 0.f;
        for (int i = 0; i < 8; i++) { G += sg[i]; Bv += sb[i]; }
        scal[0] = G;
        scal[1] = Bv + lb[0];
    }
}

// ---------------------------------------------------------------------------
// Fused conv1d(K=3,pad=1) + bias + ReLU + LN [+ linear+exp if FINAL]
// bf16x3 split: D = Ah*Bh + Al*Bh + Ah*Bl  (fp32 accumulate)
// CTA: 256 thr (8 warps, 2M x 4N), tile M=64 x N=256, 2 CTAs/SM.
// K = 768 in 24 chunks of 32 (tap-major), cp.async double-buffered.
// All fragment loads via ldmatrix.x4 (conflict-free 80B row strides).
// ---------------------------------------------------------------------------
#define SA_H 0
#define SA_L 5120
#define SB_H 10240
#define SB_L 30720
#define STAGE 51200
#define STAGE0_OFF 4096
#define CONV_SMEM (STAGE0_OFF + 2 * STAGE)   // 106496

__device__ __forceinline__ void load_chunk(
    uint32_t stg, int c, int tid, int l0, size_t rowbase,
    const __nv_bfloat16* __restrict__ Ahi, const __nv_bfloat16* __restrict__ Alo,
    const uint32_t* __restrict__ Wph, const uint32_t* __restrict__ Wpl)
{
    const int tap  = c >> 3;
    const int cin0 = (c & 7) << 5;
    // A: 64 rows x 64B (4 segs of 16B); one (row,seg) per thread
    {
        int row = tid >> 2, seg = tid & 3;
        int gl = l0 + row + tap - 1;
        int ok = (gl >= 0 && gl < Lz) ? 16 : 0;
        int glc = gl < 0 ? 0 : (gl >= Lz ? Lz - 1 : gl);
        size_t off = ((rowbase + glc) << 8) + cin0 + (seg << 3);
        uint32_t d = row * 80 + seg * 16;
        cp16(stg + SA_H + d, Ahi + off, ok);
        cp16(stg + SA_L + d, Alo + off, ok);
    }
    // B: 256 n x 16 pairs u32 (4 segs of 16B per n)
    const int p0 = (c & 7) << 4;
    const uint32_t* bh = Wph + (size_t)tap * 256 * 128 + p0;
    const uint32_t* bl = Wpl + (size_t)tap * 256 * 128 + p0;
#pragma unroll
    for (int i = 0; i < 4; ++i) {
        int idx = tid + (i << 8);            // 0..1023
        int n = idx >> 2, seg = idx & 3;
        uint32_t d = n * 80 + seg * 16;
        cp16(stg + SB_H + d, bh + n * 128 + seg * 4, 16);
        cp16(stg + SB_L + d, bl + n * 128 + seg * 4, 16);
    }
}

template<bool FINAL>
__global__ void __launch_bounds__(256, 2)
conv_mma2(const __nv_bfloat16* __restrict__ Ahi, const __nv_bfloat16* __restrict__ Alo,
          const uint32_t* __restrict__ Wph, const uint32_t* __restrict__ Wpl,
          const float* __restrict__ bias, const float* __restrict__ gamma,
          const float* __restrict__ beta, const float* __restrict__ glw,
          const float* __restrict__ scal,
          __nv_bfloat16* __restrict__ outhi, __nv_bfloat16* __restrict__ outlo,
          float* __restrict__ dur)
{
    extern __shared__ char smem[];
    const uint32_t sb = smem_u32(smem);
    float* svec = (float*)smem;                       // [4][256]
    const uint32_t stage0 = sb + STAGE0_OFF;

    const int tid = threadIdx.x;
    const int wid = tid >> 5, lane = tid & 31;
    const int wm = wid >> 2, wn = wid & 3;            // 2M x 4N warps
    const int grp = lane >> 2, tig = lane & 3;

    const int blk = blockIdx.x;                       // 0..383
    const int batch = blk / 12;
    const int l0 = (blk % 12) * 64;
    const size_t rowbase = (size_t)batch * Lz;

    svec[tid]       = bias[tid];
    svec[256 + tid] = gamma[tid];
    svec[512 + tid] = beta[tid];
    svec[768 + tid] = FINAL ? glw[tid] : 0.f;

    // ldmatrix per-lane byte offsets (within a stage)
    // A: matrices (rows 0-7, k0-7),(rows 8-15, k0-7),(rows 0-7, k8-15),(rows 8-15, k8-15)
    const uint32_t a_off = (uint32_t)((wm * 32 + (lane & 15)) * 80 + (lane >> 4) * 16);
    // B: matrices (n0-7, k0-7),(n0-7, k8-15),(n8-15, k0-7),(n8-15, k8-15)
    const uint32_t b_row = (uint32_t)(wn * 64 + ((lane & 7) | ((lane >> 4) << 3)));
    const uint32_t b_off = b_row * 80 + (((lane >> 3) & 1) * 16);

    float acc[2][8][4];
#pragma unroll
    for (int mt = 0; mt < 2; mt++)
#pragma unroll
        for (int nt = 0; nt < 8; nt++)
#pragma unroll
            for (int i = 0; i < 4; i++) acc[mt][nt][i] = 0.f;

    load_chunk(stage0,         0, tid, l0, rowbase, Ahi, Alo, Wph, Wpl);
    CP_COMMIT();
    load_chunk(stage0 + STAGE, 1, tid, l0, rowbase, Ahi, Alo, Wph, Wpl);
    CP_COMMIT();

    for (int c = 0; c < 24; ++c) {
        const uint32_t stg = stage0 + (c & 1) * STAGE;
        if (c < 23) CP_WAIT(1); else CP_WAIT(0);
        __syncthreads();

#pragma unroll
        for (int kt = 0; kt < 2; ++kt) {
            uint32_t ah[2][4], al[2][4];
#pragma unroll
            for (int mt = 0; mt < 2; ++mt) {
                LDSM_X4(ah[mt], stg + SA_H + a_off + mt * (16 * 80) + kt * 32);
                LDSM_X4(al[mt], stg + SA_L + a_off + mt * (16 * 80) + kt * 32);
            }
#pragma unroll
            for (int j = 0; j < 4; ++j) {          // covers nt = 2j, 2j+1
                uint32_t bh[4], bl[4];
                LDSM_X4(bh, stg + SB_H + b_off + j * (16 * 80) + kt * 32);
                LDSM_X4(bl, stg + SB_L + b_off + j * (16 * 80) + kt * 32);
#pragma unroll
                for (int h = 0; h < 2; ++h) {
                    int nt = j * 2 + h;
                    uint32_t b0h = bh[h * 2], b1h = bh[h * 2 + 1];
                    uint32_t b0l = bl[h * 2], b1l = bl[h * 2 + 1];
#pragma unroll
                    for (int mt = 0; mt < 2; ++mt) {
                        mma16816(acc[mt][nt], ah[mt], b0h, b1h);
                        mma16816(acc[mt][nt], al[mt], b0h, b1h);
                        mma16816(acc[mt][nt], ah[mt], b0l, b1l);
                    }
                }
            }
        }
        __syncthreads();
        if (c + 2 < 24) {
            load_chunk(stg, c + 2, tid, l0, rowbase, Ahi, Alo, Wph, Wpl);
            CP_COMMIT();
        }
    }

    // ----- epilogue: overlay reduction arrays on stage0 region -----
    float* part = (float*)(smem + STAGE0_OFF);    // [3][64][4]
    float* smu  = part + 3 * 64 * 4;              // [64]
    float* srs  = smu + 64;                       // [64]

#pragma unroll
    for (int mt = 0; mt < 2; ++mt)
#pragma unroll
        for (int hf = 0; hf < 2; ++hf) {
            float s = 0.f, sq = 0.f, sd = 0.f;
#pragma unroll
            for (int nt = 0; nt < 8; ++nt) {
                int col = wn * 64 + nt * 8 + 2 * tig;
                float v0 = fmaxf(acc[mt][nt][hf * 2 + 0] + svec[col], 0.f);
                float v1 = fmaxf(acc[mt][nt][hf * 2 + 1] + svec[col + 1], 0.f);
                acc[mt][nt][hf * 2 + 0] = v0;
                acc[mt][nt][hf * 2 + 1] = v1;
                s += v0 + v1;
                sq += v0 * v0 + v1 * v1;
                if (FINAL) sd += v0 * svec[768 + col] + v1 * svec[768 + col + 1];
            }
            s  += __shfl_xor_sync(0xffffffffu, s, 1);
            s  += __shfl_xor_sync(0xffffffffu, s, 2);
            sq += __shfl_xor_sync(0xffffffffu, sq, 1);
            sq += __shfl_xor_sync(0xffffffffu, sq, 2);
            if (FINAL) {
                sd += __shfl_xor_sync(0xffffffffu, sd, 1);
                sd += __shfl_xor_sync(0xffffffffu, sd, 2);
            }
            if (tig == 0) {
                int row = wm * 32 + mt * 16 + hf * 8 + grp;
                part[0 * 256 + row * 4 + wn] = s;
                part[1 * 256 + row * 4 + wn] = sq;
                if (FINAL) part[2 * 256 + row * 4 + wn] = sd;
            }
        }
    __syncthreads();

    if (tid < 64) {
        int row = tid;
        float s  = part[row * 4] + part[row * 4 + 1] + part[row * 4 + 2] + part[row * 4 + 3];
        float sq = part[256 + row * 4] + part[256 + row * 4 + 1] +
                   part[256 + row * 4 + 2] + part[256 + row * 4 + 3];
        float mu  = s * (1.f / 256.f);
        float var = sq * (1.f / 256.f) - mu * mu;
        float rs  = rsqrtf(var + 1e-5f);
        if (FINAL) {
            float s3 = part[512 + row * 4] + part[512 + row * 4 + 1] +
                       part[512 + row * 4 + 2] + part[512 + row * 4 + 3];
            dur[(size_t)blk * 64 + row] = expf(rs * (s3 - mu * scal[0]) + scal[1]);
        } else {
            smu[row] = mu;
            srs[row] = rs;
        }
    }

    if (!FINAL) {
        __syncthreads();
#pragma unroll
        for (int mt = 0; mt < 2; ++mt)
#pragma unroll
            for (int hf = 0; hf < 2; ++hf) {
                int row = wm * 32 + mt * 16 + hf * 8 + grp;
                float mu = smu[row], rs = srs[row];
#pragma unroll
                for (int nt = 0; nt < 8; ++nt) {
                    int col = wn * 64 + nt * 8 + 2 * tig;
                    float v0 = (acc[mt][nt][hf * 2 + 0] - mu) * rs * svec[256 + col]     + svec[512 + col];
                    float v1 = (acc[mt][nt][hf * 2 + 1] - mu) * rs * svec[256 + col + 1] + svec[512 + col + 1];
                    uint32_t hi, lo;
                    split2(v0, v1, hi, lo);
                    size_t off = ((size_t)blk * 64 + row) * 256 + col;
                    *(uint32_t*)(outhi + off) = hi;
                    *(uint32_t*)(outlo + off) = lo;
                }
            }
    }
}

// ---------------------------------------------------------------------------
// Per-batch inclusive cumsum of target (L=768) + write dpo (as float).
// ---------------------------------------------------------------------------
__global__ __launch_bounds__(768)
void cumsum_kernel(const int* __restrict__ target,
                   float* __restrict__ dpo_out)
{
    __shared__ int s[Lz];
    const int b = blockIdx.x;
    const int tid = threadIdx.x;

    int tv = target[(size_t)b * Lz + tid];
    s[tid] = tv;
    for (int off = 1; off < Lz; off <<= 1) {
        __syncthreads();
        int v = (tid >= off) ? s[tid - off] : 0;
        __syncthreads();
        s[tid] += v;
    }
    __syncthreads();
    g_cum[(size_t)b * Lz + tid] = s[tid];
    dpo_out[(size_t)b * Lz + tid] = (float)tv;
}

// ---------------------------------------------------------------------------
// LR gather: out[b,t,:] = x[b, upper_bound(cum_b, t), :] * (t < total_b)
// ---------------------------------------------------------------------------
__global__ __launch_bounds__(256)
void gather_kernel(const float* __restrict__ x,
                   float* __restrict__ dout)
{
    __shared__ int cum[Lz];
    const int b   = blockIdx.y;
    const int tid = threadIdx.x;

    for (int i = tid; i < Lz; i += 256)
        cum[i] = g_cum[(size_t)b * Lz + i];
    __syncthreads();

    const int total = cum[Lz - 1];
    const int t0 = blockIdx.x * 64;
    const int sub  = tid & 63;
    const int tloc = tid >> 6;

    const float4* xrow = (const float4*)(x + (size_t)b * Lz * Dz);
    float4* orow = (float4*)(dout + (size_t)b * Tz * Dz);

#pragma unroll 4
    for (int it = 0; it < 16; ++it) {
        int t = t0 + it * 4 + tloc;
        int lo = 0, hi = Lz;
        while (lo < hi) {
            int mid = (lo + hi) >> 1;
            if (cum[mid] <= t) lo = mid + 1; else hi = mid;
        }
        float4 v;
        if (t < total) {
            int idx = min(lo, Lz - 1);
            v = xrow[(size_t)idx * 64 + sub];
        } else {
            v = make_float4(0.0f, 0.0f, 0.0f, 0.0f);
        }
        orow[(size_t)t * 64 + sub] = v;
    }
}

// ---------------------------------------------------------------------------
// Launch
// ---------------------------------------------------------------------------
extern "C" void kernel_launch(void* const* d_in, const int* in_sizes, int n_in,
                              void* d_out, int out_size)
{
    const float* x       = (const float*)d_in[0];
    const int*   target  = (const int*)  d_in[1];
    const float* conv1_w = (const float*)d_in[3];
    const float* conv1_b = (const float*)d_in[4];
    const float* ln1_g   = (const float*)d_in[5];
    const float* ln1_b   = (const float*)d_in[6];
    const float* conv2_w = (const float*)d_in[7];
    const float* conv2_b = (const float*)d_in[8];
    const float* ln2_g   = (const float*)d_in[9];
    const float* ln2_b   = (const float*)d_in[10];
    const float* lin_w   = (const float*)d_in[11];
    const float* lin_b   = (const float*)d_in[12];

    float* out_gather = (float*)d_out;                        // [B, T, D]
    float* out_dpo    = out_gather + (size_t)Bz * Tz * Dz;    // [B, L]
    float* out_dur    = out_dpo + (size_t)Bz * Lz;            // [B, L]

    __nv_bfloat16 *xhi, *xlo, *h1h, *h1l;
    uint32_t *w1ph, *w1pl, *w2ph, *w2pl;
    float *glw, *scal;
    cudaGetSymbolAddress((void**)&xhi,  g_xhi);
    cudaGetSymbolAddress((void**)&xlo,  g_xlo);
    cudaGetSymbolAddress((void**)&h1h,  g_h1h);
    cudaGetSymbolAddress((void**)&h1l,  g_h1l);
    cudaGetSymbolAddress((void**)&w1ph, g_w1ph);
    cudaGetSymbolAddress((void**)&w1pl, g_w1pl);
    cudaGetSymbolAddress((void**)&w2ph, g_w2ph);
    cudaGetSymbolAddress((void**)&w2pl, g_w2pl);
    cudaGetSymbolAddress((void**)&glw,  g_glw);
    cudaGetSymbolAddress((void**)&scal, g_scal);

    cudaFuncSetAttribute(conv_mma2<false>, cudaFuncAttributeMaxDynamicSharedMemorySize, CONV_SMEM);
    cudaFuncSetAttribute(conv_mma2<true>,  cudaFuncAttributeMaxDynamicSharedMemorySize, CONV_SMEM);

    // Prep
    prep_x<<<(Bz * Lz * Dz) / (256 * 8), 256>>>(x, xhi, xlo);
    prep_w<<<dim3(384, 2), 256>>>(conv1_w, conv2_w, w1ph, w1pl, w2ph, w2pl);
    prep_scal<<<1, 256>>>(ln2_g, ln2_b, lin_w, lin_b, glw, scal);

    // Fused duration-predictor path (bf16x3 split-precision GEMMs)
    conv_mma2<false><<<384, 256, CONV_SMEM>>>(xhi, xlo, w1ph, w1pl, conv1_b, ln1_g, ln1_b,
                                              glw, scal, h1h, h1l, nullptr);
    conv_mma2<true ><<<384, 256, CONV_SMEM>>>(h1h, h1l, w2ph, w2pl, conv2_b, ln2_g, ln2_b,
                                              glw, scal, nullptr, nullptr, out_dur);

    // dpo + cumsum
    cumsum_kernel<<<Bz, Lz>>>(target, out_dpo);

    // Length-regulator gather
    dim3 ggrid(Tz / 64, Bz);
    gather_kernel<<<ggrid, 256>>>(x, out_gather);
}

// round 7
// speedup vs baseline: 2.2495x; 1.0061x over previous
#include <cuda_runtime.h>
#include <cuda_bf16.h>
#include <math.h>
#include <stdint.h>

#define Bz 32
#define Lz 768
#define Dz 256
#define Fz 256
#define Tz 3072

// ---------------------------------------------------------------------------
// Scratch (allocation-free: __device__ globals)
// ---------------------------------------------------------------------------
__device__ __nv_bfloat16 g_xhi[Bz * Lz * Dz];
__device__ __nv_bfloat16 g_xlo[Bz * Lz * Dz];
__device__ __nv_bfloat16 g_h1h[Bz * Lz * Fz];
__device__ __nv_bfloat16 g_h1l[Bz * Lz * Fz];
// weights re-packed: [tap][cout][pair] u32, pair = (bf16 cin=2p, cin=2p+1)
__device__ uint32_t g_w1ph[3 * 256 * 128];
__device__ uint32_t g_w1pl[3 * 256 * 128];
__device__ uint32_t g_w2ph[3 * 256 * 128];
__device__ uint32_t g_w2pl[3 * 256 * 128];
__device__ float    g_glw[256];                 // ln2_g * lin_w
__device__ float    g_scal[2];                  // {sum(g*lw), sum(b*lw)+lin_b}
__device__ int      g_cum[Bz * Lz];

// ---------------------------------------------------------------------------
// helpers
// ---------------------------------------------------------------------------
__device__ __forceinline__ uint32_t smem_u32(const void* p) {
    uint32_t a;
    asm("{ .reg .u64 t; cvta.to.shared.u64 t, %1; cvt.u32.u64 %0, t; }"
        : "=r"(a) : "l"(p));
    return a;
}

// cp.async 16B with zero-fill (src_bytes = 0 or 16)
__device__ __forceinline__ void cp16(uint32_t dst, const void* src, int src_bytes) {
    asm volatile("cp.async.cg.shared.global [%0], [%1], 16, %2;"
                 :: "r"(dst), "l"(src), "r"(src_bytes) : "memory");
}
#define CP_COMMIT() asm volatile("cp.async.commit_group;" ::: "memory")
#define CP_WAIT(n)  asm volatile("cp.async.wait_group %0;" :: "n"(n) : "memory")

#define LDSM_X4(r, addr) \
    asm volatile("ldmatrix.sync.aligned.m8n8.x4.shared.b16 {%0,%1,%2,%3}, [%4];" \
        : "=r"((r)[0]), "=r"((r)[1]), "=r"((r)[2]), "=r"((r)[3]) : "r"(addr))

// NOTE: intentionally NOT volatile — register-only op; lets ptxas reorder /
// software-pipeline so dependent accumulator chains are broken up.
__device__ __forceinline__ void mma16816(float* c, const uint32_t* a,
                                         uint32_t b0, uint32_t b1)
{
    asm("mma.sync.aligned.m16n8k16.row.col.f32.bf16.bf16.f32 "
        "{%0,%1,%2,%3}, {%4,%5,%6,%7}, {%8,%9}, {%0,%1,%2,%3};\n"
        : "+f"(c[0]), "+f"(c[1]), "+f"(c[2]), "+f"(c[3])
        : "r"(a[0]), "r"(a[1]), "r"(a[2]), "r"(a[3]), "r"(b0), "r"(b1));
}

__device__ __forceinline__ void split2(float a, float b, uint32_t& hi, uint32_t& lo)
{
    __nv_bfloat162 h = __floats2bfloat162_rn(a, b);
    float ra = a - __bfloat162float(h.x);
    float rb = b - __bfloat162float(h.y);
    __nv_bfloat162 l = __floats2bfloat162_rn(ra, rb);
    hi = *(uint32_t*)&h;
    lo = *(uint32_t*)&l;
}

// ---------------------------------------------------------------------------
// Prep kernels
// ---------------------------------------------------------------------------
__global__ __launch_bounds__(256)
void prep_x(const float* __restrict__ x,
            __nv_bfloat16* __restrict__ ohi, __nv_bfloat16* __restrict__ olo)
{
    size_t i = ((size_t)blockIdx.x * 256 + threadIdx.x) * 8;
    float4 f0 = *(const float4*)(x + i);
    float4 f1 = *(const float4*)(x + i + 4);
    uint4 vh, vl;
    split2(f0.x, f0.y, vh.x, vl.x);
    split2(f0.z, f0.w, vh.y, vl.y);
    split2(f1.x, f1.y, vh.z, vl.z);
    split2(f1.z, f1.w, vh.w, vl.w);
    *(uint4*)(ohi + i) = vh;
    *(uint4*)(olo + i) = vl;
}

// weights [3,256,256] (tap,cin,cout) fp32 -> [tap][cout][pair] split u32
__global__ __launch_bounds__(256)
void prep_w(const float* __restrict__ w1, const float* __restrict__ w2,
            uint32_t* __restrict__ p1h, uint32_t* __restrict__ p1l,
            uint32_t* __restrict__ p2h, uint32_t* __restrict__ p2l)
{
    int idx = blockIdx.x * 256 + threadIdx.x;          // 0 .. 98303
    const float* w = blockIdx.y ? w2 : w1;
    uint32_t* ph = blockIdx.y ? p2h : p1h;
    uint32_t* pl = blockIdx.y ? p2l : p1l;
    int p   = idx & 127;
    int n   = (idx >> 7) & 255;
    int tap = idx >> 15;
    float a = w[((size_t)(tap * 256 + 2 * p))     * 256 + n];
    float b = w[((size_t)(tap * 256 + 2 * p + 1)) * 256 + n];
    uint32_t hi, lo;
    split2(a, b, hi, lo);
    ph[idx] = hi;
    pl[idx] = lo;
}

__global__ __launch_bounds__(256)
void prep_scal(const float* __restrict__ g, const float* __restrict__ bb,
               const float* __restrict__ lw, const float* __restrict__ lb,
               float* __restrict__ glw, float* __restrict__ scal)
{
    __shared__ float sg[8], sb[8];
    int t = threadIdx.x;
    float lwv = lw[t];
    float gv = g[t] * lwv;
    float bv = bb[t] * lwv;
    glw[t] = gv;
#pragma unroll
    for (int o = 16; o; o >>= 1) {
        gv += __shfl_xor_sync(0xffffffffu, gv, o);
        bv += __shfl_xor_sync(0xffffffffu, bv, o);
    }
    if ((t & 31) == 0) { sg[t >> 5] = gv; sb[t >> 5] = bv; }
    __syncthreads();
    if (t == 0) {
        float G = 0.f, Bv = 0.f;
        for (int i = 0; i < 8; i++) { G += sg[i]; Bv += sb[i]; }
        scal[0] = G;
        scal[1] = Bv + lb[0];
    }
}

// ---------------------------------------------------------------------------
// Fused conv1d(K=3,pad=1) + bias + ReLU + LN [+ linear+exp if FINAL]
// bf16x3 split: D = Ah*Bh + Al*Bh + Ah*Bl  (fp32 accumulate)
// CTA: 256 thr (8 warps, 2M x 4N), tile M=64 x N=256, 2 CTAs/SM.
// K = 768 in 24 chunks of 32 (tap-major), cp.async double-buffered.
// Fragment loads via ldmatrix.x4; MMAs scheduled pass-major (non-volatile asm)
// so dependent accumulator chains are >=4 apart and ptxas can pipeline.
// ---------------------------------------------------------------------------
#define SA_H 0
#define SA_L 5120
#define SB_H 10240
#define SB_L 30720
#define STAGE 51200
#define STAGE0_OFF 4096
#define CONV_SMEM (STAGE0_OFF + 2 * STAGE)   // 106496

__device__ __forceinline__ void load_chunk(
    uint32_t stg, int c, int tid, int l0, size_t rowbase,
    const __nv_bfloat16* __restrict__ Ahi, const __nv_bfloat16* __restrict__ Alo,
    const uint32_t* __restrict__ Wph, const uint32_t* __restrict__ Wpl)
{
    const int tap  = c >> 3;
    const int cin0 = (c & 7) << 5;
    // A: 64 rows x 64B (4 segs of 16B); one (row,seg) per thread
    {
        int row = tid >> 2, seg = tid & 3;
        int gl = l0 + row + tap - 1;
        int ok = (gl >= 0 && gl < Lz) ? 16 : 0;
        int glc = gl < 0 ? 0 : (gl >= Lz ? Lz - 1 : gl);
        size_t off = ((rowbase + glc) << 8) + cin0 + (seg << 3);
        uint32_t d = row * 80 + seg * 16;
        cp16(stg + SA_H + d, Ahi + off, ok);
        cp16(stg + SA_L + d, Alo + off, ok);
    }
    // B: 256 n x 16 pairs u32 (4 segs of 16B per n)
    const int p0 = (c & 7) << 4;
    const uint32_t* bh = Wph + (size_t)tap * 256 * 128 + p0;
    const uint32_t* bl = Wpl + (size_t)tap * 256 * 128 + p0;
#pragma unroll
    for (int i = 0; i < 4; ++i) {
        int idx = tid + (i << 8);            // 0..1023
        int n = idx >> 2, seg = idx & 3;
        uint32_t d = n * 80 + seg * 16;
        cp16(stg + SB_H + d, bh + n * 128 + seg * 4, 16);
        cp16(stg + SB_L + d, bl + n * 128 + seg * 4, 16);
    }
}

template<bool FINAL>
__global__ void __launch_bounds__(256, 2)
conv_mma2(const __nv_bfloat16* __restrict__ Ahi, const __nv_bfloat16* __restrict__ Alo,
          const uint32_t* __restrict__ Wph, const uint32_t* __restrict__ Wpl,
          const float* __restrict__ bias, const float* __restrict__ gamma,
          const float* __restrict__ beta, const float* __restrict__ glw,
          const float* __restrict__ scal,
          __nv_bfloat16* __restrict__ outhi, __nv_bfloat16* __restrict__ outlo,
          float* __restrict__ dur)
{
    extern __shared__ char smem[];
    const uint32_t sb = smem_u32(smem);
    float* svec = (float*)smem;                       // [4][256]
    const uint32_t stage0 = sb + STAGE0_OFF;

    const int tid = threadIdx.x;
    const int wid = tid >> 5, lane = tid & 31;
    const int wm = wid >> 2, wn = wid & 3;            // 2M x 4N warps
    const int grp = lane >> 2, tig = lane & 3;

    const int blk = blockIdx.x;                       // 0..383
    const int batch = blk / 12;
    const int l0 = (blk % 12) * 64;
    const size_t rowbase = (size_t)batch * Lz;

    svec[tid]       = bias[tid];
    svec[256 + tid] = gamma[tid];
    svec[512 + tid] = beta[tid];
    svec[768 + tid] = FINAL ? glw[tid] : 0.f;

    // ldmatrix per-lane byte offsets (within a stage)
    const uint32_t a_off = (uint32_t)((wm * 32 + (lane & 15)) * 80 + (lane >> 4) * 16);
    const uint32_t b_row = (uint32_t)(wn * 64 + ((lane & 7) | ((lane >> 4) << 3)));
    const uint32_t b_off = b_row * 80 + (((lane >> 3) & 1) * 16);

    float acc[2][8][4];
#pragma unroll
    for (int mt = 0; mt < 2; mt++)
#pragma unroll
        for (int nt = 0; nt < 8; nt++)
#pragma unroll
            for (int i = 0; i < 4; i++) acc[mt][nt][i] = 0.f;

    load_chunk(stage0,         0, tid, l0, rowbase, Ahi, Alo, Wph, Wpl);
    CP_COMMIT();
    load_chunk(stage0 + STAGE, 1, tid, l0, rowbase, Ahi, Alo, Wph, Wpl);
    CP_COMMIT();

    for (int c = 0; c < 24; ++c) {
        const uint32_t stg = stage0 + (c & 1) * STAGE;
        if (c < 23) CP_WAIT(1); else CP_WAIT(0);
        __syncthreads();

#pragma unroll
        for (int kt = 0; kt < 2; ++kt) {
            uint32_t ah[2][4], al[2][4];
#pragma unroll
            for (int mt = 0; mt < 2; ++mt) {
                LDSM_X4(ah[mt], stg + SA_H + a_off + mt * (16 * 80) + kt * 32);
                LDSM_X4(al[mt], stg + SA_L + a_off + mt * (16 * 80) + kt * 32);
            }
#pragma unroll
            for (int j = 0; j < 4; ++j) {          // covers nt = 2j, 2j+1
                uint32_t bh[4], bl[4];
                LDSM_X4(bh, stg + SB_H + b_off + j * (16 * 80) + kt * 32);
                LDSM_X4(bl, stg + SB_L + b_off + j * (16 * 80) + kt * 32);
                // pass-major issue order: each accumulator touched once per
                // pass -> dependent MMAs >=4 apart; non-volatile asm lets
                // ptxas interleave across j as well.
#pragma unroll
                for (int h = 0; h < 2; ++h)
#pragma unroll
                    for (int mt = 0; mt < 2; ++mt)
                        mma16816(acc[mt][j * 2 + h], ah[mt], bh[h * 2], bh[h * 2 + 1]);
#pragma unroll
                for (int h = 0; h < 2; ++h)
#pragma unroll
                    for (int mt = 0; mt < 2; ++mt)
                        mma16816(acc[mt][j * 2 + h], al[mt], bh[h * 2], bh[h * 2 + 1]);
#pragma unroll
                for (int h = 0; h < 2; ++h)
#pragma unroll
                    for (int mt = 0; mt < 2; ++mt)
                        mma16816(acc[mt][j * 2 + h], ah[mt], bl[h * 2], bl[h * 2 + 1]);
            }
        }
        __syncthreads();
        if (c + 2 < 24) {
            load_chunk(stg, c + 2, tid, l0, rowbase, Ahi, Alo, Wph, Wpl);
            CP_COMMIT();
        }
    }

    // ----- epilogue: overlay reduction arrays on stage0 region -----
    float* part = (float*)(smem + STAGE0_OFF);    // [3][64][4]
    float* smu  = part + 3 * 64 * 4;              // [64]
    float* srs  = smu + 64;                       // [64]

#pragma unroll
    for (int mt = 0; mt < 2; ++mt)
#pragma unroll
        for (int hf = 0; hf < 2; ++hf) {
            float s = 0.f, sq = 0.f, sd = 0.f;
#pragma unroll
            for (int nt = 0; nt < 8; ++nt) {
                int col = wn * 64 + nt * 8 + 2 * tig;
                float v0 = fmaxf(acc[mt][nt][hf * 2 + 0] + svec[col], 0.f);
                float v1 = fmaxf(acc[mt][nt][hf * 2 + 1] + svec[col + 1], 0.f);
                acc[mt][nt][hf * 2 + 0] = v0;
                acc[mt][nt][hf * 2 + 1] = v1;
                s += v0 + v1;
                sq += v0 * v0 + v1 * v1;
                if (FINAL) sd += v0 * svec[768 + col] + v1 * svec[768 + col + 1];
            }
            s  += __shfl_xor_sync(0xffffffffu, s, 1);
            s  += __shfl_xor_sync(0xffffffffu, s, 2);
            sq += __shfl_xor_sync(0xffffffffu, sq, 1);
            sq += __shfl_xor_sync(0xffffffffu, sq, 2);
            if (FINAL) {
                sd += __shfl_xor_sync(0xffffffffu, sd, 1);
                sd += __shfl_xor_sync(0xffffffffu, sd, 2);
            }
            if (tig == 0) {
                int row = wm * 32 + mt * 16 + hf * 8 + grp;
                part[0 * 256 + row * 4 + wn] = s;
                part[1 * 256 + row * 4 + wn] = sq;
                if (FINAL) part[2 * 256 + row * 4 + wn] = sd;
            }
        }
    __syncthreads();

    if (tid < 64) {
        int row = tid;
        float s  = part[row * 4] + part[row * 4 + 1] + part[row * 4 + 2] + part[row * 4 + 3];
        float sq = part[256 + row * 4] + part[256 + row * 4 + 1] +
                   part[256 + row * 4 + 2] + part[256 + row * 4 + 3];
        float mu  = s * (1.f / 256.f);
        float var = sq * (1.f / 256.f) - mu * mu;
        float rs  = rsqrtf(var + 1e-5f);
        if (FINAL) {
            float s3 = part[512 + row * 4] + part[512 + row * 4 + 1] +
                       part[512 + row * 4 + 2] + part[512 + row * 4 + 3];
            dur[(size_t)blk * 64 + row] = expf(rs * (s3 - mu * scal[0]) + scal[1]);
        } else {
            smu[row] = mu;
            srs[row] = rs;
        }
    }

    if (!FINAL) {
        __syncthreads();
#pragma unroll
        for (int mt = 0; mt < 2; ++mt)
#pragma unroll
            for (int hf = 0; hf < 2; ++hf) {
                int row = wm * 32 + mt * 16 + hf * 8 + grp;
                float mu = smu[row], rs = srs[row];
#pragma unroll
                for (int nt = 0; nt < 8; ++nt) {
                    int col = wn * 64 + nt * 8 + 2 * tig;
                    float v0 = (acc[mt][nt][hf * 2 + 0] - mu) * rs * svec[256 + col]     + svec[512 + col];
                    float v1 = (acc[mt][nt][hf * 2 + 1] - mu) * rs * svec[256 + col + 1] + svec[512 + col + 1];
                    uint32_t hi, lo;
                    split2(v0, v1, hi, lo);
                    size_t off = ((size_t)blk * 64 + row) * 256 + col;
                    *(uint32_t*)(outhi + off) = hi;
                    *(uint32_t*)(outlo + off) = lo;
                }
            }
    }
}

// ---------------------------------------------------------------------------
// Per-batch inclusive cumsum of target (L=768) + write dpo (as float).
// ---------------------------------------------------------------------------
__global__ __launch_bounds__(768)
void cumsum_kernel(const int* __restrict__ target,
                   float* __restrict__ dpo_out)
{
    __shared__ int s[Lz];
    const int b = blockIdx.x;
    const int tid = threadIdx.x;

    int tv = target[(size_t)b * Lz + tid];
    s[tid] = tv;
    for (int off = 1; off < Lz; off <<= 1) {
        __syncthreads();
        int v = (tid >= off) ? s[tid - off] : 0;
        __syncthreads();
        s[tid] += v;
    }
    __syncthreads();
    g_cum[(size_t)b * Lz + tid] = s[tid];
    dpo_out[(size_t)b * Lz + tid] = (float)tv;
}

// ---------------------------------------------------------------------------
// LR gather: out[b,t,:] = x[b, upper_bound(cum_b, t), :] * (t < total_b)
// ---------------------------------------------------------------------------
__global__ __launch_bounds__(256)
void gather_kernel(const float* __restrict__ x,
                   float* __restrict__ dout)
{
    __shared__ int cum[Lz];
    const int b   = blockIdx.y;
    const int tid = threadIdx.x;

    for (int i = tid; i < Lz; i += 256)
        cum[i] = g_cum[(size_t)b * Lz + i];
    __syncthreads();

    const int total = cum[Lz - 1];
    const int t0 = blockIdx.x * 64;
    const int sub  = tid & 63;
    const int tloc = tid >> 6;

    const float4* xrow = (const float4*)(x + (size_t)b * Lz * Dz);
    float4* orow = (float4*)(dout + (size_t)b * Tz * Dz);

#pragma unroll 4
    for (int it = 0; it < 16; ++it) {
        int t = t0 + it * 4 + tloc;
        int lo = 0, hi = Lz;
        while (lo < hi) {
            int mid = (lo + hi) >> 1;
            if (cum[mid] <= t) lo = mid + 1; else hi = mid;
        }
        float4 v;
        if (t < total) {
            int idx = min(lo, Lz - 1);
            v = xrow[(size_t)idx * 64 + sub];
        } else {
            v = make_float4(0.0f, 0.0f, 0.0f, 0.0f);
        }
        orow[(size_t)t * 64 + sub] = v;
    }
}

// ---------------------------------------------------------------------------
// Launch
// ---------------------------------------------------------------------------
extern "C" void kernel_launch(void* const* d_in, const int* in_sizes, int n_in,
                              void* d_out, int out_size)
{
    const float* x       = (const float*)d_in[0];
    const int*   target  = (const int*)  d_in[1];
    const float* conv1_w = (const float*)d_in[3];
    const float* conv1_b = (const float*)d_in[4];
    const float* ln1_g   = (const float*)d_in[5];
    const float* ln1_b   = (const float*)d_in[6];
    const float* conv2_w = (const float*)d_in[7];
    const float* conv2_b = (const float*)d_in[8];
    const float* ln2_g   = (const float*)d_in[9];
    const float* ln2_b   = (const float*)d_in[10];
    const float* lin_w   = (const float*)d_in[11];
    const float* lin_b   = (const float*)d_in[12];

    float* out_gather = (float*)d_out;                        // [B, T, D]
    float* out_dpo    = out_gather + (size_t)Bz * Tz * Dz;    // [B, L]
    float* out_dur    = out_dpo + (size_t)Bz * Lz;            // [B, L]

    __nv_bfloat16 *xhi, *xlo, *h1h, *h1l;
    uint32_t *w1ph, *w1pl, *w2ph, *w2pl;
    float *glw, *scal;
    cudaGetSymbolAddress((void**)&xhi,  g_xhi);
    cudaGetSymbolAddress((void**)&xlo,  g_xlo);
    cudaGetSymbolAddress((void**)&h1h,  g_h1h);
    cudaGetSymbolAddress((void**)&h1l,  g_h1l);
    cudaGetSymbolAddress((void**)&w1ph, g_w1ph);
    cudaGetSymbolAddress((void**)&w1pl, g_w1pl);
    cudaGetSymbolAddress((void**)&w2ph, g_w2ph);
    cudaGetSymbolAddress((void**)&w2pl, g_w2pl);
    cudaGetSymbolAddress((void**)&glw,  g_glw);
    cudaGetSymbolAddress((void**)&scal, g_scal);

    cudaFuncSetAttribute(conv_mma2<false>, cudaFuncAttributeMaxDynamicSharedMemorySize, CONV_SMEM);
    cudaFuncSetAttribute(conv_mma2<true>,  cudaFuncAttributeMaxDynamicSharedMemorySize, CONV_SMEM);

    // Prep
    prep_x<<<(Bz * Lz * Dz) / (256 * 8), 256>>>(x, xhi, xlo);
    prep_w<<<dim3(384, 2), 256>>>(conv1_w, conv2_w, w1ph, w1pl, w2ph, w2pl);
    prep_scal<<<1, 256>>>(ln2_g, ln2_b, lin_w, lin_b, glw, scal);

    // Fused duration-predictor path (bf16x3 split-precision GEMMs)
    conv_mma2<false><<<384, 256, CONV_SMEM>>>(xhi, xlo, w1ph, w1pl, conv1_b, ln1_g, ln1_b,
                                              glw, scal, h1h, h1l, nullptr);
    conv_mma2<true ><<<384, 256, CONV_SMEM>>>(h1h, h1l, w2ph, w2pl, conv2_b, ln2_g, ln2_b,
                                              glw, scal, nullptr, nullptr, out_dur);

    // dpo + cumsum
    cumsum_kernel<<<Bz, Lz>>>(target, out_dpo);

    // Length-regulator gather
    dim3 ggrid(Tz / 64, Bz);
    gather_kernel<<<ggrid, 256>>>(x, out_gather);
}

// round 9
// speedup vs baseline: 2.2829x; 1.0148x over previous
#include <cuda_runtime.h>
#include <cuda_bf16.h>
#include <math.h>
#include <stdint.h>

#define Bz 32
#define Lz 768
#define Dz 256
#define Fz 256
#define Tz 3072

#define NCONV 384          // conv tile CTAs per layer kernel

// prep_all dispatch ranges
#define PREP_X_BLOCKS 3072         // (Bz*Lz*Dz) / (256*8)
#define PREP_W_BLOCKS 768          // 2 * 98304 / 256
#define PREP_TOTAL (PREP_X_BLOCKS + PREP_W_BLOCKS + 1)   // 3841

// ---------------------------------------------------------------------------
// Scratch (allocation-free: __device__ globals)
// ---------------------------------------------------------------------------
__device__ __nv_bfloat16 g_xhi[Bz * Lz * Dz];
__device__ __nv_bfloat16 g_xlo[Bz * Lz * Dz];
__device__ __nv_bfloat16 g_h1h[Bz * Lz * Fz];
__device__ __nv_bfloat16 g_h1l[Bz * Lz * Fz];
// weights re-packed: [tap][cout][pair] u32, pair = (bf16 cin=2p, cin=2p+1)
__device__ uint32_t g_w1ph[3 * 256 * 128];
__device__ uint32_t g_w1pl[3 * 256 * 128];
__device__ uint32_t g_w2ph[3 * 256 * 128];
__device__ uint32_t g_w2pl[3 * 256 * 128];
__device__ float    g_glw[256];                 // ln2_g * lin_w
__device__ float    g_scal[2];                  // {sum(g*lw), sum(b*lw)+lin_b}
__device__ int      g_cum[Bz * Lz];

// ---------------------------------------------------------------------------
// helpers
// ---------------------------------------------------------------------------
__device__ __forceinline__ uint32_t smem_u32(const void* p) {
    uint32_t a;
    asm("{ .reg .u64 t; cvta.to.shared.u64 t, %1; cvt.u32.u64 %0, t; }"
        : "=r"(a) : "l"(p));
    return a;
}

// cp.async 16B with zero-fill (src_bytes = 0 or 16)
__device__ __forceinline__ void cp16(uint32_t dst, const void* src, int src_bytes) {
    asm volatile("cp.async.cg.shared.global [%0], [%1], 16, %2;"
                 :: "r"(dst), "l"(src), "r"(src_bytes) : "memory");
}
#define CP_COMMIT() asm volatile("cp.async.commit_group;" ::: "memory")
#define CP_WAIT(n)  asm volatile("cp.async.wait_group %0;" :: "n"(n) : "memory")

#define LDSM_X4(r, addr) \
    asm volatile("ldmatrix.sync.aligned.m8n8.x4.shared.b16 {%0,%1,%2,%3}, [%4];" \
        : "=r"((r)[0]), "=r"((r)[1]), "=r"((r)[2]), "=r"((r)[3]) : "r"(addr))

__device__ __forceinline__ void mma16816(float* c, const uint32_t* a,
                                         uint32_t b0, uint32_t b1)
{
    asm("mma.sync.aligned.m16n8k16.row.col.f32.bf16.bf16.f32 "
        "{%0,%1,%2,%3}, {%4,%5,%6,%7}, {%8,%9}, {%0,%1,%2,%3};\n"
        : "+f"(c[0]), "+f"(c[1]), "+f"(c[2]), "+f"(c[3])
        : "r"(a[0]), "r"(a[1]), "r"(a[2]), "r"(a[3]), "r"(b0), "r"(b1));
}

__device__ __forceinline__ void split2(float a, float b, uint32_t& hi, uint32_t& lo)
{
    __nv_bfloat162 h = __floats2bfloat162_rn(a, b);
    float ra = a - __bfloat162float(h.x);
    float rb = b - __bfloat162float(h.y);
    __nv_bfloat162 l = __floats2bfloat162_rn(ra, rb);
    hi = *(uint32_t*)&h;
    lo = *(uint32_t*)&l;
}

// ---------------------------------------------------------------------------
// Unified prep kernel (block-range dispatch):
//   blk <  3072           : x fp32 -> split bf16 (8 elems/thread)
//   3072 <= blk < 3840    : weights -> [tap][cout][pair] split u32
//   blk == 3840           : glw / scal scalars
// ---------------------------------------------------------------------------
__global__ __launch_bounds__(256)
void prep_all(const float* __restrict__ x,
              __nv_bfloat16* __restrict__ ohi, __nv_bfloat16* __restrict__ olo,
              const float* __restrict__ w1, const float* __restrict__ w2,
              uint32_t* __restrict__ p1h, uint32_t* __restrict__ p1l,
              uint32_t* __restrict__ p2h, uint32_t* __restrict__ p2l,
              const float* __restrict__ g, const float* __restrict__ bb,
              const float* __restrict__ lw, const float* __restrict__ lb,
              float* __restrict__ glw, float* __restrict__ scal)
{
    const int blk = blockIdx.x;
    const int t = threadIdx.x;

    if (blk < PREP_X_BLOCKS) {
        size_t i = ((size_t)blk * 256 + t) * 8;
        float4 f0 = *(const float4*)(x + i);
        float4 f1 = *(const float4*)(x + i + 4);
        uint4 vh, vl;
        split2(f0.x, f0.y, vh.x, vl.x);
        split2(f0.z, f0.w, vh.y, vl.y);
        split2(f1.x, f1.y, vh.z, vl.z);
        split2(f1.z, f1.w, vh.w, vl.w);
        *(uint4*)(ohi + i) = vh;
        *(uint4*)(olo + i) = vl;
        return;
    }
    if (blk < PREP_X_BLOCKS + PREP_W_BLOCKS) {
        int e = blk - PREP_X_BLOCKS;                   // 0..767
        int sel = e >= 384;
        int idx = (e - sel * 384) * 256 + t;           // 0 .. 98303
        const float* w = sel ? w2 : w1;
        uint32_t* ph = sel ? p2h : p1h;
        uint32_t* pl = sel ? p2l : p1l;
        int p   = idx & 127;
        int n   = (idx >> 7) & 255;
        int tap = idx >> 15;
        float a = w[((size_t)(tap * 256 + 2 * p))     * 256 + n];
        float b = w[((size_t)(tap * 256 + 2 * p + 1)) * 256 + n];
        uint32_t hi, lo;
        split2(a, b, hi, lo);
        ph[idx] = hi;
        pl[idx] = lo;
        return;
    }
    // scalars
    {
        __shared__ float sg[8], sb[8];
        float lwv = lw[t];
        float gv = g[t] * lwv;
        float bv = bb[t] * lwv;
        glw[t] = gv;
#pragma unroll
        for (int o = 16; o; o >>= 1) {
            gv += __shfl_xor_sync(0xffffffffu, gv, o);
            bv += __shfl_xor_sync(0xffffffffu, bv, o);
        }
        if ((t & 31) == 0) { sg[t >> 5] = gv; sb[t >> 5] = bv; }
        __syncthreads();
        if (t == 0) {
            float G = 0.f, Bv = 0.f;
            for (int i = 0; i < 8; i++) { G += sg[i]; Bv += sb[i]; }
            scal[0] = G;
            scal[1] = Bv + lb[0];
        }
    }
}

// ---------------------------------------------------------------------------
// Extra-CTA payloads (run in conv kernels' grids, filling wave-2 idle slots)
// ---------------------------------------------------------------------------
// cumsum for one batch, 256 threads (each handles 3 contiguous elements)
__device__ void cumsum_block(int b, const int* __restrict__ target,
                             float* __restrict__ dpo_out, char* smem)
{
    int* ps = (int*)smem;               // [256] partials
    const int t = threadIdx.x;
    const size_t base = (size_t)b * Lz + 3 * t;
    int v0 = target[base], v1 = target[base + 1], v2 = target[base + 2];
    int s1 = v0 + v1, s2 = s1 + v2;
    ps[t] = s2;
    __syncthreads();
#pragma unroll
    for (int off = 1; off < 256; off <<= 1) {
        int u = (t >= off) ? ps[t - off] : 0;
        __syncthreads();
        ps[t] += u;
        __syncthreads();
    }
    int pre = (t > 0) ? ps[t - 1] : 0;
    g_cum[base]     = pre + v0;
    g_cum[base + 1] = pre + s1;
    g_cum[base + 2] = pre + s2;
    dpo_out[base]     = (float)v0;
    dpo_out[base + 1] = (float)v1;
    dpo_out[base + 2] = (float)v2;
}

// gather for one (batch, 64-t block): e in 0..1535, b = e/48, tpart = e%48
__device__ void gather_block(int e, const float* __restrict__ x,
                             float* __restrict__ dout, char* smem)
{
    int* cum = (int*)smem;              // [768]
    const int b = e / 48;
    const int tpart = e % 48;
    const int tid = threadIdx.x;

    for (int i = tid; i < Lz; i += 256)
        cum[i] = g_cum[(size_t)b * Lz + i];
    __syncthreads();

    const int total = cum[Lz - 1];
    const int t0 = tpart * 64;
    const int sub  = tid & 63;
    const int tloc = tid >> 6;

    const float4* xrow = (const float4*)(x + (size_t)b * Lz * Dz);
    float4* orow = (float4*)(dout + (size_t)b * Tz * Dz);

#pragma unroll 4
    for (int it = 0; it < 16; ++it) {
        int t = t0 + it * 4 + tloc;
        int lo = 0, hi = Lz;
        while (lo < hi) {
            int mid = (lo + hi) >> 1;
            if (cum[mid] <= t) lo = mid + 1; else hi = mid;
        }
        float4 v;
        if (t < total) {
            int idx = min(lo, Lz - 1);
            v = xrow[(size_t)idx * 64 + sub];
        } else {
            v = make_float4(0.0f, 0.0f, 0.0f, 0.0f);
        }
        orow[(size_t)t * 64 + sub] = v;
    }
}

// ---------------------------------------------------------------------------
// Fused conv1d(K=3,pad=1) + bias + ReLU + LN [+ linear+exp if FINAL]
// bf16x3 split: D = Ah*Bh + Al*Bh + Ah*Bl  (fp32 accumulate)
// CTA: 256 thr (8 warps, 2M x 4N), tile M=64 x N=256, 2 CTAs/SM.
// Extra CTAs (blk >= NCONV): cumsum (layer 1) / gather (layer 2) payloads
// that fill the wave-2 idle slots.
// ---------------------------------------------------------------------------
#define SA_H 0
#define SA_L 5120
#define SB_H 10240
#define SB_L 30720
#define STAGE 51200
#define STAGE0_OFF 4096
#define CONV_SMEM (STAGE0_OFF + 2 * STAGE)   // 106496

__device__ __forceinline__ void load_chunk(
    uint32_t stg, int c, int tid, int l0, size_t rowbase,
    const __nv_bfloat16* __restrict__ Ahi, const __nv_bfloat16* __restrict__ Alo,
    const uint32_t* __restrict__ Wph, const uint32_t* __restrict__ Wpl)
{
    const int tap  = c >> 3;
    const int cin0 = (c & 7) << 5;
    // A: 64 rows x 64B (4 segs of 16B); one (row,seg) per thread
    {
        int row = tid >> 2, seg = tid & 3;
        int gl = l0 + row + tap - 1;
        int ok = (gl >= 0 && gl < Lz) ? 16 : 0;
        int glc = gl < 0 ? 0 : (gl >= Lz ? Lz - 1 : gl);
        size_t off = ((rowbase + glc) << 8) + cin0 + (seg << 3);
        uint32_t d = row * 80 + seg * 16;
        cp16(stg + SA_H + d, Ahi + off, ok);
        cp16(stg + SA_L + d, Alo + off, ok);
    }
    // B: 256 n x 16 pairs u32 (4 segs of 16B per n)
    const int p0 = (c & 7) << 4;
    const uint32_t* bh = Wph + (size_t)tap * 256 * 128 + p0;
    const uint32_t* bl = Wpl + (size_t)tap * 256 * 128 + p0;
#pragma unroll
    for (int i = 0; i < 4; ++i) {
        int idx = tid + (i << 8);            // 0..1023
        int n = idx >> 2, seg = idx & 3;
        uint32_t d = n * 80 + seg * 16;
        cp16(stg + SB_H + d, bh + n * 128 + seg * 4, 16);
        cp16(stg + SB_L + d, bl + n * 128 + seg * 4, 16);
    }
}

template<bool FINAL>
__global__ void __launch_bounds__(256, 2)
conv_mma2(const __nv_bfloat16* __restrict__ Ahi, const __nv_bfloat16* __restrict__ Alo,
          const uint32_t* __restrict__ Wph, const uint32_t* __restrict__ Wpl,
          const float* __restrict__ bias, const float* __restrict__ gamma,
          const float* __restrict__ beta, const float* __restrict__ glw,
          const float* __restrict__ scal,
          __nv_bfloat16* __restrict__ outhi, __nv_bfloat16* __restrict__ outlo,
          float* __restrict__ dur,
          const int* __restrict__ target, float* __restrict__ dpo_out,  // layer1 extra
          const float* __restrict__ xg, float* __restrict__ gout)       // layer2 extra
{
    extern __shared__ char smem[];
    const int blk = blockIdx.x;

    // ---- extra-CTA payloads (fill wave-2 idle slots) ----
    if (blk >= NCONV) {
        if (FINAL) gather_block(blk - NCONV, xg, gout, smem);
        else       cumsum_block(blk - NCONV, target, dpo_out, smem);
        return;
    }

    const uint32_t sb = smem_u32(smem);
    float* svec = (float*)smem;                       // [4][256]
    const uint32_t stage0 = sb + STAGE0_OFF;

    const int tid = threadIdx.x;
    const int wid = tid >> 5, lane = tid & 31;
    const int wm = wid >> 2, wn = wid & 3;            // 2M x 4N warps
    const int grp = lane >> 2, tig = lane & 3;

    const int batch = blk / 12;
    const int l0 = (blk % 12) * 64;
    const size_t rowbase = (size_t)batch * Lz;

    svec[tid]       = bias[tid];
    svec[256 + tid] = gamma[tid];
    svec[512 + tid] = beta[tid];
    svec[768 + tid] = FINAL ? glw[tid] : 0.f;

    // ldmatrix per-lane byte offsets (within a stage)
    const uint32_t a_off = (uint32_t)((wm * 32 + (lane & 15)) * 80 + (lane >> 4) * 16);
    const uint32_t b_row = (uint32_t)(wn * 64 + ((lane & 7) | ((lane >> 4) << 3)));
    const uint32_t b_off = b_row * 80 + (((lane >> 3) & 1) * 16);

    float acc[2][8][4];
#pragma unroll
    for (int mt = 0; mt < 2; mt++)
#pragma unroll
        for (int nt = 0; nt < 8; nt++)
#pragma unroll
            for (int i = 0; i < 4; i++) acc[mt][nt][i] = 0.f;

    load_chunk(stage0,         0, tid, l0, rowbase, Ahi, Alo, Wph, Wpl);
    CP_COMMIT();
    load_chunk(stage0 + STAGE, 1, tid, l0, rowbase, Ahi, Alo, Wph, Wpl);
    CP_COMMIT();

    for (int c = 0; c < 24; ++c) {
        const uint32_t stg = stage0 + (c & 1) * STAGE;
        if (c < 23) CP_WAIT(1); else CP_WAIT(0);
        __syncthreads();

#pragma unroll
        for (int kt = 0; kt < 2; ++kt) {
            uint32_t ah[2][4], al[2][4];
#pragma unroll
            for (int mt = 0; mt < 2; ++mt) {
                LDSM_X4(ah[mt], stg + SA_H + a_off + mt * (16 * 80) + kt * 32);
                LDSM_X4(al[mt], stg + SA_L + a_off + mt * (16 * 80) + kt * 32);
            }
#pragma unroll
            for (int j = 0; j < 4; ++j) {          // covers nt = 2j, 2j+1
                uint32_t bh[4], bl[4];
                LDSM_X4(bh, stg + SB_H + b_off + j * (16 * 80) + kt * 32);
                LDSM_X4(bl, stg + SB_L + b_off + j * (16 * 80) + kt * 32);
#pragma unroll
                for (int h = 0; h < 2; ++h)
#pragma unroll
                    for (int mt = 0; mt < 2; ++mt)
                        mma16816(acc[mt][j * 2 + h], ah[mt], bh[h * 2], bh[h * 2 + 1]);
#pragma unroll
                for (int h = 0; h < 2; ++h)
#pragma unroll
                    for (int mt = 0; mt < 2; ++mt)
                        mma16816(acc[mt][j * 2 + h], al[mt], bh[h * 2], bh[h * 2 + 1]);
#pragma unroll
                for (int h = 0; h < 2; ++h)
#pragma unroll
                    for (int mt = 0; mt < 2; ++mt)
                        mma16816(acc[mt][j * 2 + h], ah[mt], bl[h * 2], bl[h * 2 + 1]);
            }
        }
        __syncthreads();
        if (c + 2 < 24) {
            load_chunk(stg, c + 2, tid, l0, rowbase, Ahi, Alo, Wph, Wpl);
            CP_COMMIT();
        }
    }

    // ----- epilogue: overlay reduction arrays on stage0 region -----
    float* part = (float*)(smem + STAGE0_OFF);    // [3][64][4]
    float* smu  = part + 3 * 64 * 4;              // [64]
    float* srs  = smu + 64;                       // [64]

#pragma unroll
    for (int mt = 0; mt < 2; ++mt)
#pragma unroll
        for (int hf = 0; hf < 2; ++hf) {
            float s = 0.f, sq = 0.f, sd = 0.f;
#pragma unroll
            for (int nt = 0; nt < 8; ++nt) {
                int col = wn * 64 + nt * 8 + 2 * tig;
                float v0 = fmaxf(acc[mt][nt][hf * 2 + 0] + svec[col], 0.f);
                float v1 = fmaxf(acc[mt][nt][hf * 2 + 1] + svec[col + 1], 0.f);
                acc[mt][nt][hf * 2 + 0] = v0;
                acc[mt][nt][hf * 2 + 1] = v1;
                s += v0 + v1;
                sq += v0 * v0 + v1 * v1;
                if (FINAL) sd += v0 * svec[768 + col] + v1 * svec[768 + col + 1];
            }
            s  += __shfl_xor_sync(0xffffffffu, s, 1);
            s  += __shfl_xor_sync(0xffffffffu, s, 2);
            sq += __shfl_xor_sync(0xffffffffu, sq, 1);
            sq += __shfl_xor_sync(0xffffffffu, sq, 2);
            if (FINAL) {
                sd += __shfl_xor_sync(0xffffffffu, sd, 1);
                sd += __shfl_xor_sync(0xffffffffu, sd, 2);
            }
            if (tig == 0) {
                int row = wm * 32 + mt * 16 + hf * 8 + grp;
                part[0 * 256 + row * 4 + wn] = s;
                part[1 * 256 + row * 4 + wn] = sq;
                if (FINAL) part[2 * 256 + row * 4 + wn] = sd;
            }
        }
    __syncthreads();

    if (tid < 64) {
        int row = tid;
        float s  = part[row * 4] + part[row * 4 + 1] + part[row * 4 + 2] + part[row * 4 + 3];
        float sq = part[256 + row * 4] + part[256 + row * 4 + 1] +
                   part[256 + row * 4 + 2] + part[256 + row * 4 + 3];
        float mu  = s * (1.f / 256.f);
        float var = sq * (1.f / 256.f) - mu * mu;
        float rs  = rsqrtf(var + 1e-5f);
        if (FINAL) {
            float s3 = part[512 + row * 4] + part[512 + row * 4 + 1] +
                       part[512 + row * 4 + 2] + part[512 + row * 4 + 3];
            dur[(size_t)blk * 64 + row] = expf(rs * (s3 - mu * scal[0]) + scal[1]);
        } else {
            smu[row] = mu;
            srs[row] = rs;
        }
    }

    if (!FINAL) {
        __syncthreads();
#pragma unroll
        for (int mt = 0; mt < 2; ++mt)
#pragma unroll
            for (int hf = 0; hf < 2; ++hf) {
                int row = wm * 32 + mt * 16 + hf * 8 + grp;
                float mu = smu[row], rs = srs[row];
#pragma unroll
                for (int nt = 0; nt < 8; ++nt) {
                    int col = wn * 64 + nt * 8 + 2 * tig;
                    float v0 = (acc[mt][nt][hf * 2 + 0] - mu) * rs * svec[256 + col]     + svec[512 + col];
                    float v1 = (acc[mt][nt][hf * 2 + 1] - mu) * rs * svec[256 + col + 1] + svec[512 + col + 1];
                    uint32_t hi, lo;
                    split2(v0, v1, hi, lo);
                    size_t off = ((size_t)blk * 64 + row) * 256 + col;
                    *(uint32_t*)(outhi + off) = hi;
                    *(uint32_t*)(outlo + off) = lo;
                }
            }
    }
}

// ---------------------------------------------------------------------------
// Launch
// ---------------------------------------------------------------------------
extern "C" void kernel_launch(void* const* d_in, const int* in_sizes, int n_in,
                              void* d_out, int out_size)
{
    const float* x       = (const float*)d_in[0];
    const int*   target  = (const int*)  d_in[1];
    const float* conv1_w = (const float*)d_in[3];
    const float* conv1_b = (const float*)d_in[4];
    const float* ln1_g   = (const float*)d_in[5];
    const float* ln1_b   = (const float*)d_in[6];
    const float* conv2_w = (const float*)d_in[7];
    const float* conv2_b = (const float*)d_in[8];
    const float* ln2_g   = (const float*)d_in[9];
    const float* ln2_b   = (const float*)d_in[10];
    const float* lin_w   = (const float*)d_in[11];
    const float* lin_b   = (const float*)d_in[12];

    float* out_gather = (float*)d_out;                        // [B, T, D]
    float* out_dpo    = out_gather + (size_t)Bz * Tz * Dz;    // [B, L]
    float* out_dur    = out_dpo + (size_t)Bz * Lz;            // [B, L]

    __nv_bfloat16 *xhi, *xlo, *h1h, *h1l;
    uint32_t *w1ph, *w1pl, *w2ph, *w2pl;
    float *glw, *scal;
    cudaGetSymbolAddress((void**)&xhi,  g_xhi);
    cudaGetSymbolAddress((void**)&xlo,  g_xlo);
    cudaGetSymbolAddress((void**)&h1h,  g_h1h);
    cudaGetSymbolAddress((void**)&h1l,  g_h1l);
    cudaGetSymbolAddress((void**)&w1ph, g_w1ph);
    cudaGetSymbolAddress((void**)&w1pl, g_w1pl);
    cudaGetSymbolAddress((void**)&w2ph, g_w2ph);
    cudaGetSymbolAddress((void**)&w2pl, g_w2pl);
    cudaGetSymbolAddress((void**)&glw,  g_glw);
    cudaGetSymbolAddress((void**)&scal, g_scal);

    cudaFuncSetAttribute(conv_mma2<false>, cudaFuncAttributeMaxDynamicSharedMemorySize, CONV_SMEM);
    cudaFuncSetAttribute(conv_mma2<true>,  cudaFuncAttributeMaxDynamicSharedMemorySize, CONV_SMEM);

    // Prep: single kernel (x split | weight repack | scalars)
    prep_all<<<PREP_TOTAL, 256>>>(x, xhi, xlo, conv1_w, conv2_w,
                                  w1ph, w1pl, w2ph, w2pl,
                                  ln2_g, ln2_b, lin_w, lin_b, glw, scal);

    // Layer 1: conv tiles (0..383) + cumsum extras (384..415)
    conv_mma2<false><<<NCONV + Bz, 256, CONV_SMEM>>>(
        xhi, xlo, w1ph, w1pl, conv1_b, ln1_g, ln1_b, glw, scal,
        h1h, h1l, nullptr, target, out_dpo, nullptr, nullptr);

    // Layer 2: conv tiles (0..383) + gather extras (384..1919)
    conv_mma2<true><<<NCONV + 48 * Bz, 256, CONV_SMEM>>>(
        h1h, h1l, w2ph, w2pl, conv2_b, ln2_g, ln2_b, glw, scal,
        nullptr, nullptr, out_dur, nullptr, nullptr, x, out_gather);
}

// round 10
// speedup vs baseline: 2.4606x; 1.0778x over previous
#include <cuda_runtime.h>
#include <cuda_bf16.h>
#include <math.h>
#include <stdint.h>

#define Bz 32
#define Lz 768
#define Dz 256
#define Fz 256
#define Tz 3072

#define NCONV 384
// fused grid block ranges
#define BLK_C1   0                      // 384 conv1 tiles
#define BLK_CS   (BLK_C1 + NCONV)       // 32 cumsum
#define BLK_C2   (BLK_CS + Bz)          // 384 conv2 tiles
#define BLK_GA   (BLK_C2 + NCONV)       // 1536 gather
#define BLK_TOTAL (BLK_GA + 48 * Bz)    // 2336

// prep_all dispatch ranges
#define PREP_X_BLOCKS 3072
#define PREP_W_BLOCKS 768
#define PREP_TOTAL (PREP_X_BLOCKS + PREP_W_BLOCKS + 1)   // 3841

#define NFLAGS (NCONV + Bz)             // conv1 tile flags + cumsum flags

// ---------------------------------------------------------------------------
// Scratch (allocation-free: __device__ globals)
// ---------------------------------------------------------------------------
__device__ __nv_bfloat16 g_xhi[Bz * Lz * Dz];
__device__ __nv_bfloat16 g_xlo[Bz * Lz * Dz];
__device__ __nv_bfloat16 g_h1h[Bz * Lz * Fz];
__device__ __nv_bfloat16 g_h1l[Bz * Lz * Fz];
__device__ uint32_t g_w1ph[3 * 256 * 128];
__device__ uint32_t g_w1pl[3 * 256 * 128];
__device__ uint32_t g_w2ph[3 * 256 * 128];
__device__ uint32_t g_w2pl[3 * 256 * 128];
__device__ float    g_glw[256];
__device__ float    g_scal[2];
__device__ int      g_cum[Bz * Lz];
__device__ int      g_flag[NFLAGS];

// ---------------------------------------------------------------------------
// helpers
// ---------------------------------------------------------------------------
__device__ __forceinline__ uint32_t smem_u32(const void* p) {
    uint32_t a;
    asm("{ .reg .u64 t; cvta.to.shared.u64 t, %1; cvt.u32.u64 %0, t; }"
        : "=r"(a) : "l"(p));
    return a;
}

__device__ __forceinline__ void cp16(uint32_t dst, const void* src, int src_bytes) {
    asm volatile("cp.async.cg.shared.global [%0], [%1], 16, %2;"
                 :: "r"(dst), "l"(src), "r"(src_bytes) : "memory");
}
#define CP_COMMIT() asm volatile("cp.async.commit_group;" ::: "memory")
#define CP_WAIT(n)  asm volatile("cp.async.wait_group %0;" :: "n"(n) : "memory")

#define LDSM_X4(r, addr) \
    asm volatile("ldmatrix.sync.aligned.m8n8.x4.shared.b16 {%0,%1,%2,%3}, [%4];" \
        : "=r"((r)[0]), "=r"((r)[1]), "=r"((r)[2]), "=r"((r)[3]) : "r"(addr))

__device__ __forceinline__ void mma16816(float* c, const uint32_t* a,
                                         uint32_t b0, uint32_t b1)
{
    asm("mma.sync.aligned.m16n8k16.row.col.f32.bf16.bf16.f32 "
        "{%0,%1,%2,%3}, {%4,%5,%6,%7}, {%8,%9}, {%0,%1,%2,%3};\n"
        : "+f"(c[0]), "+f"(c[1]), "+f"(c[2]), "+f"(c[3])
        : "r"(a[0]), "r"(a[1]), "r"(a[2]), "r"(a[3]), "r"(b0), "r"(b1));
}

__device__ __forceinline__ void split2(float a, float b, uint32_t& hi, uint32_t& lo)
{
    __nv_bfloat162 h = __floats2bfloat162_rn(a, b);
    float ra = a - __bfloat162float(h.x);
    float rb = b - __bfloat162float(h.y);
    __nv_bfloat162 l = __floats2bfloat162_rn(ra, rb);
    hi = *(uint32_t*)&h;
    lo = *(uint32_t*)&l;
}

// writer: done producing -> publish
__device__ __forceinline__ void flag_publish(int idx) {
    __threadfence();
    if (threadIdx.x == 0) atomicExch(&g_flag[idx], 1);
}
// reader: thread 0 spins; caller must __syncthreads() after
__device__ __forceinline__ void flag_spin(int idx) {
    if (threadIdx.x == 0) {
        while (atomicAdd(&g_flag[idx], 0) == 0) __nanosleep(64);
    }
}

// ---------------------------------------------------------------------------
// Unified prep kernel:
//   blk <  3072           : x fp32 -> split bf16
//   3072 <= blk < 3840    : weights -> [tap][cout][pair] split u32
//   blk == 3840           : glw / scal scalars + dependency-flag reset
// ---------------------------------------------------------------------------
__global__ __launch_bounds__(256)
void prep_all(const float* __restrict__ x,
              __nv_bfloat16* __restrict__ ohi, __nv_bfloat16* __restrict__ olo,
              const float* __restrict__ w1, const float* __restrict__ w2,
              uint32_t* __restrict__ p1h, uint32_t* __restrict__ p1l,
              uint32_t* __restrict__ p2h, uint32_t* __restrict__ p2l,
              const float* __restrict__ g, const float* __restrict__ bb,
              const float* __restrict__ lw, const float* __restrict__ lb,
              float* __restrict__ glw, float* __restrict__ scal)
{
    const int blk = blockIdx.x;
    const int t = threadIdx.x;

    if (blk < PREP_X_BLOCKS) {
        size_t i = ((size_t)blk * 256 + t) * 8;
        float4 f0 = *(const float4*)(x + i);
        float4 f1 = *(const float4*)(x + i + 4);
        uint4 vh, vl;
        split2(f0.x, f0.y, vh.x, vl.x);
        split2(f0.z, f0.w, vh.y, vl.y);
        split2(f1.x, f1.y, vh.z, vl.z);
        split2(f1.z, f1.w, vh.w, vl.w);
        *(uint4*)(ohi + i) = vh;
        *(uint4*)(olo + i) = vl;
        return;
    }
    if (blk < PREP_X_BLOCKS + PREP_W_BLOCKS) {
        int e = blk - PREP_X_BLOCKS;
        int sel = e >= 384;
        int idx = (e - sel * 384) * 256 + t;
        const float* w = sel ? w2 : w1;
        uint32_t* ph = sel ? p2h : p1h;
        uint32_t* pl = sel ? p2l : p1l;
        int p   = idx & 127;
        int n   = (idx >> 7) & 255;
        int tap = idx >> 15;
        float a = w[((size_t)(tap * 256 + 2 * p))     * 256 + n];
        float b = w[((size_t)(tap * 256 + 2 * p + 1)) * 256 + n];
        uint32_t hi, lo;
        split2(a, b, hi, lo);
        ph[idx] = hi;
        pl[idx] = lo;
        return;
    }
    // scalars + flag reset
    {
        for (int i = t; i < NFLAGS; i += 256) g_flag[i] = 0;
        __shared__ float sg[8], sb[8];
        float lwv = lw[t];
        float gv = g[t] * lwv;
        float bv = bb[t] * lwv;
        glw[t] = gv;
#pragma unroll
        for (int o = 16; o; o >>= 1) {
            gv += __shfl_xor_sync(0xffffffffu, gv, o);
            bv += __shfl_xor_sync(0xffffffffu, bv, o);
        }
        if ((t & 31) == 0) { sg[t >> 5] = gv; sb[t >> 5] = bv; }
        __syncthreads();
        if (t == 0) {
            float G = 0.f, Bv = 0.f;
            for (int i = 0; i < 8; i++) { G += sg[i]; Bv += sb[i]; }
            scal[0] = G;
            scal[1] = Bv + lb[0];
        }
    }
}

// ---------------------------------------------------------------------------
// cumsum for one batch (256 threads, 3 elems each)
// ---------------------------------------------------------------------------
__device__ void cumsum_block(int b, const int* __restrict__ target,
                             float* __restrict__ dpo_out, char* smem)
{
    int* ps = (int*)smem;
    const int t = threadIdx.x;
    const size_t base = (size_t)b * Lz + 3 * t;
    int v0 = target[base], v1 = target[base + 1], v2 = target[base + 2];
    int s1 = v0 + v1, s2 = s1 + v2;
    ps[t] = s2;
    __syncthreads();
#pragma unroll
    for (int off = 1; off < 256; off <<= 1) {
        int u = (t >= off) ? ps[t - off] : 0;
        __syncthreads();
        ps[t] += u;
        __syncthreads();
    }
    int pre = (t > 0) ? ps[t - 1] : 0;
    g_cum[base]     = pre + v0;
    g_cum[base + 1] = pre + s1;
    g_cum[base + 2] = pre + s2;
    dpo_out[base]     = (float)v0;
    dpo_out[base + 1] = (float)v1;
    dpo_out[base + 2] = (float)v2;
    flag_publish(NCONV + b);
}

// ---------------------------------------------------------------------------
// gather for one (batch, 64-t block): e in 0..1535
// ---------------------------------------------------------------------------
__device__ void gather_block(int e, const float* __restrict__ x,
                             float* __restrict__ dout, char* smem)
{
    int* cum = (int*)smem;
    const int b = e / 48;
    const int tpart = e % 48;
    const int tid = threadIdx.x;

    flag_spin(NCONV + b);
    __syncthreads();

    for (int i = tid; i < Lz; i += 256)
        cum[i] = g_cum[(size_t)b * Lz + i];
    __syncthreads();

    const int total = cum[Lz - 1];
    const int t0 = tpart * 64;
    const int sub  = tid & 63;
    const int tloc = tid >> 6;

    const float4* xrow = (const float4*)(x + (size_t)b * Lz * Dz);
    float4* orow = (float4*)(dout + (size_t)b * Tz * Dz);

#pragma unroll 4
    for (int it = 0; it < 16; ++it) {
        int t = t0 + it * 4 + tloc;
        int lo = 0, hi = Lz;
        while (lo < hi) {
            int mid = (lo + hi) >> 1;
            if (cum[mid] <= t) lo = mid + 1; else hi = mid;
        }
        float4 v;
        if (t < total) {
            int idx = min(lo, Lz - 1);
            v = xrow[(size_t)idx * 64 + sub];
        } else {
            v = make_float4(0.0f, 0.0f, 0.0f, 0.0f);
        }
        orow[(size_t)t * 64 + sub] = v;
    }
}

// ---------------------------------------------------------------------------
// conv tile body (shared by both layers; fin selects conv2 fused linear+exp)
// ---------------------------------------------------------------------------
#define SA_H 0
#define SA_L 5120
#define SB_H 10240
#define SB_L 30720
#define STAGE 51200
#define STAGE0_OFF 4096
#define CONV_SMEM (STAGE0_OFF + 2 * STAGE)   // 106496

__device__ __forceinline__ void load_chunk(
    uint32_t stg, int c, int tid, int l0, size_t rowbase,
    const __nv_bfloat16* __restrict__ Ahi, const __nv_bfloat16* __restrict__ Alo,
    const uint32_t* __restrict__ Wph, const uint32_t* __restrict__ Wpl)
{
    const int tap  = c >> 3;
    const int cin0 = (c & 7) << 5;
    {
        int row = tid >> 2, seg = tid & 3;
        int gl = l0 + row + tap - 1;
        int ok = (gl >= 0 && gl < Lz) ? 16 : 0;
        int glc = gl < 0 ? 0 : (gl >= Lz ? Lz - 1 : gl);
        size_t off = ((rowbase + glc) << 8) + cin0 + (seg << 3);
        uint32_t d = row * 80 + seg * 16;
        cp16(stg + SA_H + d, Ahi + off, ok);
        cp16(stg + SA_L + d, Alo + off, ok);
    }
    const int p0 = (c & 7) << 4;
    const uint32_t* bh = Wph + (size_t)tap * 256 * 128 + p0;
    const uint32_t* bl = Wpl + (size_t)tap * 256 * 128 + p0;
#pragma unroll
    for (int i = 0; i < 4; ++i) {
        int idx = tid + (i << 8);
        int n = idx >> 2, seg = idx & 3;
        uint32_t d = n * 80 + seg * 16;
        cp16(stg + SB_H + d, bh + n * 128 + seg * 4, 16);
        cp16(stg + SB_L + d, bl + n * 128 + seg * 4, 16);
    }
}

__device__ void conv_tile(
    int tile, bool fin, char* smem,
    const __nv_bfloat16* __restrict__ Ahi, const __nv_bfloat16* __restrict__ Alo,
    const uint32_t* __restrict__ Wph, const uint32_t* __restrict__ Wpl,
    const float* __restrict__ bias, const float* __restrict__ gamma,
    const float* __restrict__ beta, const float* __restrict__ glw,
    const float* __restrict__ scal,
    __nv_bfloat16* __restrict__ outhi, __nv_bfloat16* __restrict__ outlo,
    float* __restrict__ dur)
{
    const uint32_t sb = smem_u32(smem);
    float* svec = (float*)smem;                       // [4][256]
    const uint32_t stage0 = sb + STAGE0_OFF;

    const int tid = threadIdx.x;
    const int wid = tid >> 5, lane = tid & 31;
    const int wm = wid >> 2, wn = wid & 3;
    const int grp = lane >> 2, tig = lane & 3;

    const int batch = tile / 12;
    const int part  = tile % 12;
    const int l0 = part * 64;
    const size_t rowbase = (size_t)batch * Lz;

    // conv2: wait for producing conv1 tiles (covers halo rows)
    if (fin) {
        flag_spin(tile);
        if (part > 0)  flag_spin(tile - 1);
        if (part < 11) flag_spin(tile + 1);
        __threadfence();
    }
    __syncthreads();

    svec[tid]       = bias[tid];
    svec[256 + tid] = gamma[tid];
    svec[512 + tid] = beta[tid];
    svec[768 + tid] = fin ? glw[tid] : 0.f;

    const uint32_t a_off = (uint32_t)((wm * 32 + (lane & 15)) * 80 + (lane >> 4) * 16);
    const uint32_t b_row = (uint32_t)(wn * 64 + ((lane & 7) | ((lane >> 4) << 3)));
    const uint32_t b_off = b_row * 80 + (((lane >> 3) & 1) * 16);

    float acc[2][8][4];
#pragma unroll
    for (int mt = 0; mt < 2; mt++)
#pragma unroll
        for (int nt = 0; nt < 8; nt++)
#pragma unroll
            for (int i = 0; i < 4; i++) acc[mt][nt][i] = 0.f;

    load_chunk(stage0,         0, tid, l0, rowbase, Ahi, Alo, Wph, Wpl);
    CP_COMMIT();
    load_chunk(stage0 + STAGE, 1, tid, l0, rowbase, Ahi, Alo, Wph, Wpl);
    CP_COMMIT();

    for (int c = 0; c < 24; ++c) {
        const uint32_t stg = stage0 + (c & 1) * STAGE;
        if (c < 23) CP_WAIT(1); else CP_WAIT(0);
        __syncthreads();

#pragma unroll
        for (int kt = 0; kt < 2; ++kt) {
            uint32_t ah[2][4], al[2][4];
#pragma unroll
            for (int mt = 0; mt < 2; ++mt) {
                LDSM_X4(ah[mt], stg + SA_H + a_off + mt * (16 * 80) + kt * 32);
                LDSM_X4(al[mt], stg + SA_L + a_off + mt * (16 * 80) + kt * 32);
            }
#pragma unroll
            for (int j = 0; j < 4; ++j) {
                uint32_t bh[4], bl[4];
                LDSM_X4(bh, stg + SB_H + b_off + j * (16 * 80) + kt * 32);
                LDSM_X4(bl, stg + SB_L + b_off + j * (16 * 80) + kt * 32);
#pragma unroll
                for (int h = 0; h < 2; ++h)
#pragma unroll
                    for (int mt = 0; mt < 2; ++mt)
                        mma16816(acc[mt][j * 2 + h], ah[mt], bh[h * 2], bh[h * 2 + 1]);
#pragma unroll
                for (int h = 0; h < 2; ++h)
#pragma unroll
                    for (int mt = 0; mt < 2; ++mt)
                        mma16816(acc[mt][j * 2 + h], al[mt], bh[h * 2], bh[h * 2 + 1]);
#pragma unroll
                for (int h = 0; h < 2; ++h)
#pragma unroll
                    for (int mt = 0; mt < 2; ++mt)
                        mma16816(acc[mt][j * 2 + h], ah[mt], bl[h * 2], bl[h * 2 + 1]);
            }
        }
        __syncthreads();
        if (c + 2 < 24) {
            load_chunk(stg, c + 2, tid, l0, rowbase, Ahi, Alo, Wph, Wpl);
            CP_COMMIT();
        }
    }

    // ----- epilogue -----
    float* pa = (float*)(smem + STAGE0_OFF);      // [3][64][4]
    float* smu  = pa + 3 * 64 * 4;                // [64]
    float* srs  = smu + 64;                       // [64]

#pragma unroll
    for (int mt = 0; mt < 2; ++mt)
#pragma unroll
        for (int hf = 0; hf < 2; ++hf) {
            float s = 0.f, sq = 0.f, sd = 0.f;
#pragma unroll
            for (int nt = 0; nt < 8; ++nt) {
                int col = wn * 64 + nt * 8 + 2 * tig;
                float v0 = fmaxf(acc[mt][nt][hf * 2 + 0] + svec[col], 0.f);
                float v1 = fmaxf(acc[mt][nt][hf * 2 + 1] + svec[col + 1], 0.f);
                acc[mt][nt][hf * 2 + 0] = v0;
                acc[mt][nt][hf * 2 + 1] = v1;
                s += v0 + v1;
                sq += v0 * v0 + v1 * v1;
                if (fin) sd += v0 * svec[768 + col] + v1 * svec[768 + col + 1];
            }
            s  += __shfl_xor_sync(0xffffffffu, s, 1);
            s  += __shfl_xor_sync(0xffffffffu, s, 2);
            sq += __shfl_xor_sync(0xffffffffu, sq, 1);
            sq += __shfl_xor_sync(0xffffffffu, sq, 2);
            if (fin) {
                sd += __shfl_xor_sync(0xffffffffu, sd, 1);
                sd += __shfl_xor_sync(0xffffffffu, sd, 2);
            }
            if (tig == 0) {
                int row = wm * 32 + mt * 16 + hf * 8 + grp;
                pa[0 * 256 + row * 4 + wn] = s;
                pa[1 * 256 + row * 4 + wn] = sq;
                if (fin) pa[2 * 256 + row * 4 + wn] = sd;
            }
        }
    __syncthreads();

    if (tid < 64) {
        int row = tid;
        float s  = pa[row * 4] + pa[row * 4 + 1] + pa[row * 4 + 2] + pa[row * 4 + 3];
        float sq = pa[256 + row * 4] + pa[256 + row * 4 + 1] +
                   pa[256 + row * 4 + 2] + pa[256 + row * 4 + 3];
        float mu  = s * (1.f / 256.f);
        float var = sq * (1.f / 256.f) - mu * mu;
        float rs  = rsqrtf(var + 1e-5f);
        if (fin) {
            float s3 = pa[512 + row * 4] + pa[512 + row * 4 + 1] +
                       pa[512 + row * 4 + 2] + pa[512 + row * 4 + 3];
            dur[(size_t)tile * 64 + row] = expf(rs * (s3 - mu * scal[0]) + scal[1]);
        } else {
            smu[row] = mu;
            srs[row] = rs;
        }
    }

    if (!fin) {
        __syncthreads();
#pragma unroll
        for (int mt = 0; mt < 2; ++mt)
#pragma unroll
            for (int hf = 0; hf < 2; ++hf) {
                int row = wm * 32 + mt * 16 + hf * 8 + grp;
                float mu = smu[row], rs = srs[row];
#pragma unroll
                for (int nt = 0; nt < 8; ++nt) {
                    int col = wn * 64 + nt * 8 + 2 * tig;
                    float v0 = (acc[mt][nt][hf * 2 + 0] - mu) * rs * svec[256 + col]     + svec[512 + col];
                    float v1 = (acc[mt][nt][hf * 2 + 1] - mu) * rs * svec[256 + col + 1] + svec[512 + col + 1];
                    uint32_t hi, lo;
                    split2(v0, v1, hi, lo);
                    size_t off = ((size_t)tile * 64 + row) * 256 + col;
                    *(uint32_t*)(outhi + off) = hi;
                    *(uint32_t*)(outlo + off) = lo;
                }
            }
        flag_publish(tile);
    }
}

// ---------------------------------------------------------------------------
// Fused pipeline kernel: conv1 | cumsum | conv2(+lin+exp) | gather
// ---------------------------------------------------------------------------
__global__ void __launch_bounds__(256, 2)
fused_all(const __nv_bfloat16* __restrict__ xhi, const __nv_bfloat16* __restrict__ xlo,
          const __nv_bfloat16* __restrict__ h1h_c, const __nv_bfloat16* __restrict__ h1l_c,
          __nv_bfloat16* __restrict__ h1h, __nv_bfloat16* __restrict__ h1l,
          const uint32_t* __restrict__ w1ph, const uint32_t* __restrict__ w1pl,
          const uint32_t* __restrict__ w2ph, const uint32_t* __restrict__ w2pl,
          const float* __restrict__ conv1_b, const float* __restrict__ ln1_g,
          const float* __restrict__ ln1_b,
          const float* __restrict__ conv2_b, const float* __restrict__ ln2_g,
          const float* __restrict__ ln2_b,
          const float* __restrict__ glw, const float* __restrict__ scal,
          const int* __restrict__ target, const float* __restrict__ x,
          float* __restrict__ out_gather, float* __restrict__ out_dpo,
          float* __restrict__ out_dur)
{
    extern __shared__ char smem[];
    const int blk = blockIdx.x;

    if (blk < BLK_CS) {
        // conv1 tile
        conv_tile(blk, false, smem, xhi, xlo, w1ph, w1pl,
                  conv1_b, ln1_g, ln1_b, glw, scal, h1h, h1l, nullptr);
    } else if (blk < BLK_C2) {
        cumsum_block(blk - BLK_CS, target, out_dpo, smem);
    } else if (blk < BLK_GA) {
        // conv2 tile (waits on conv1 flags)
        conv_tile(blk - BLK_C2, true, smem, h1h_c, h1l_c, w2ph, w2pl,
                  conv2_b, ln2_g, ln2_b, glw, scal, nullptr, nullptr, out_dur);
    } else {
        gather_block(blk - BLK_GA, x, out_gather, smem);
    }
}

// ---------------------------------------------------------------------------
// Launch
// ---------------------------------------------------------------------------
extern "C" void kernel_launch(void* const* d_in, const int* in_sizes, int n_in,
                              void* d_out, int out_size)
{
    const float* x       = (const float*)d_in[0];
    const int*   target  = (const int*)  d_in[1];
    const float* conv1_w = (const float*)d_in[3];
    const float* conv1_b = (const float*)d_in[4];
    const float* ln1_g   = (const float*)d_in[5];
    const float* ln1_b   = (const float*)d_in[6];
    const float* conv2_w = (const float*)d_in[7];
    const float* conv2_b = (const float*)d_in[8];
    const float* ln2_g   = (const float*)d_in[9];
    const float* ln2_b   = (const float*)d_in[10];
    const float* lin_w   = (const float*)d_in[11];
    const float* lin_b   = (const float*)d_in[12];

    float* out_gather = (float*)d_out;                        // [B, T, D]
    float* out_dpo    = out_gather + (size_t)Bz * Tz * Dz;    // [B, L]
    float* out_dur    = out_dpo + (size_t)Bz * Lz;            // [B, L]

    __nv_bfloat16 *xhi, *xlo, *h1h, *h1l;
    uint32_t *w1ph, *w1pl, *w2ph, *w2pl;
    float *glw, *scal;
    cudaGetSymbolAddress((void**)&xhi,  g_xhi);
    cudaGetSymbolAddress((void**)&xlo,  g_xlo);
    cudaGetSymbolAddress((void**)&h1h,  g_h1h);
    cudaGetSymbolAddress((void**)&h1l,  g_h1l);
    cudaGetSymbolAddress((void**)&w1ph, g_w1ph);
    cudaGetSymbolAddress((void**)&w1pl, g_w1pl);
    cudaGetSymbolAddress((void**)&w2ph, g_w2ph);
    cudaGetSymbolAddress((void**)&w2pl, g_w2pl);
    cudaGetSymbolAddress((void**)&glw,  g_glw);
    cudaGetSymbolAddress((void**)&scal, g_scal);

    cudaFuncSetAttribute(fused_all, cudaFuncAttributeMaxDynamicSharedMemorySize, CONV_SMEM);

    // Prep: x split | weight repack | scalars + flag reset
    prep_all<<<PREP_TOTAL, 256>>>(x, xhi, xlo, conv1_w, conv2_w,
                                  w1ph, w1pl, w2ph, w2pl,
                                  ln2_g, ln2_b, lin_w, lin_b, glw, scal);

    // One fused pipeline kernel: conv1 -> (flags) -> conv2, cumsum -> gather
    fused_all<<<BLK_TOTAL, 256, CONV_SMEM>>>(
        xhi, xlo, h1h, h1l, h1h, h1l,
        w1ph, w1pl, w2ph, w2pl,
        conv1_b, ln1_g, ln1_b, conv2_b, ln2_g, ln2_b,
        glw, scal, target, x, out_gather, out_dpo, out_dur);
}